// round 9
// baseline (speedup 1.0000x reference)
#include <cuda_runtime.h>
#include <cuda_bf16.h>
#include <stdint.h>
#include <math.h>

// ---------------------------------------------------------------------------
// Shapes (fixed)
#define TOK   4096
#define DIN   4096
#define DOUT  4096
#define ELEMS ((size_t)DOUT * (size_t)DIN)

#define FAST_DECAY 0.95f
#define FAST_LR    0.05f
#define SLOW_DECAY 0.99f
#define SLOW_LR    0.01f
#define HOMEO_TARGET 5.0

// CTA tile 64x128x32(bf16), 8 warps (2m x 4n), warp tile 32x32, 2-stage cp.async
// grid = 64*32 = 2048 CTAs -> 6.92 waves over 296 slots (99% tail utilization)
#define BK      32
#define NCHUNK  (4096 / BK)          // 128
#define NTILES  2048
#define DYN_SMEM 61440               // non-TRANS stage layout x2

// ---------------------------------------------------------------------------
// Scratch
__device__ __nv_bfloat16 g_whi[ELEMS], g_wlo[ELEMS];     // w_eff split, K-major
__device__ __nv_bfloat16 g_xhi[ELEMS], g_xlo[ELEMS];     // X split [TOK, DIN]
__device__ __nv_bfloat16 g_yrhi[ELEMS], g_yrlo[ELEMS];   // relu(Y) split [TOK, DOUT]
__device__ double g_partials[NTILES];
__device__ float  g_factor;

// ---------------------------------------------------------------------------
__device__ __forceinline__ uint32_t smem_u32(const void* p) {
    uint32_t a;
    asm("{ .reg .u64 t; cvta.to.shared.u64 t, %1; cvt.u32.u64 %0, t; }" : "=r"(a) : "l"(p));
    return a;
}
__device__ __forceinline__ void mma_bf16(float* c, const uint32_t* a, const uint32_t* b) {
    asm volatile(
        "mma.sync.aligned.m16n8k16.row.col.f32.bf16.bf16.f32 "
        "{%0,%1,%2,%3}, {%4,%5,%6,%7}, {%8,%9}, {%0,%1,%2,%3};"
        : "+f"(c[0]), "+f"(c[1]), "+f"(c[2]), "+f"(c[3])
        : "r"(a[0]), "r"(a[1]), "r"(a[2]), "r"(a[3]), "r"(b[0]), "r"(b[1]));
}
#define LDSM4(R, A) \
    asm volatile("ldmatrix.sync.aligned.m8n8.x4.shared.b16 {%0,%1,%2,%3}, [%4];" \
        : "=r"((R)[0]), "=r"((R)[1]), "=r"((R)[2]), "=r"((R)[3]) : "r"(A))
#define LDSM4T(R, A) \
    asm volatile("ldmatrix.sync.aligned.m8n8.x4.trans.shared.b16 {%0,%1,%2,%3}, [%4];" \
        : "=r"((R)[0]), "=r"((R)[1]), "=r"((R)[2]), "=r"((R)[3]) : "r"(A))
#define CP_ASYNC16(dst, src) \
    asm volatile("cp.async.cg.shared.global [%0], [%1], 16;" :: "r"(dst), "l"(src))
#define CP_COMMIT() asm volatile("cp.async.commit_group;" ::: "memory")
#define CP_WAIT0()  asm volatile("cp.async.wait_group 0;" ::: "memory")

// ---------------------------------------------------------------------------
// Fused prep: blocks [0,4096): per-row quantize+combine w_eff -> whi/wlo
//             blocks [4096,20480): elementwise split X -> xhi/xlo
__global__ __launch_bounds__(256) void k_prep(
    const float* __restrict__ w, const float* __restrict__ fast, const float* __restrict__ slow,
    const float* __restrict__ x,
    __nv_bfloat16* __restrict__ whi, __nv_bfloat16* __restrict__ wlo,
    __nv_bfloat16* __restrict__ xhi, __nv_bfloat16* __restrict__ xlo)
{
    const int tid = threadIdx.x;
    if (blockIdx.x >= 4096) {
        const size_t i = ((size_t)(blockIdx.x - 4096) * 256 + tid) * 4;
        float4 v = *(const float4*)(x + i);
        union { __nv_bfloat16 b[4]; uint64_t u; } H, L;
        float f[4] = {v.x, v.y, v.z, v.w};
        #pragma unroll
        for (int j = 0; j < 4; j++) {
            __nv_bfloat16 h = __float2bfloat16_rn(f[j]);
            H.b[j] = h;
            L.b[j] = __float2bfloat16_rn(f[j] - __bfloat162float(h));
        }
        *(uint64_t*)(xhi + i) = H.u;
        *(uint64_t*)(xlo + i) = L.u;
        return;
    }
    const int row = blockIdx.x;
    const size_t base = (size_t)row * DIN;

    float s = 0.f;
    for (int i = tid; i < DIN; i += 256) s += fabsf(w[base + i]);
    __shared__ float red[256];
    red[tid] = s;
    __syncthreads();
    #pragma unroll
    for (int off = 128; off > 0; off >>= 1) {
        if (tid < off) red[tid] += red[tid + off];
        __syncthreads();
    }
    float scale = fmaxf(red[0] * (1.0f / (float)DIN), 1e-5f);
    const float inv_scale = 1.0f / scale;

    for (int i = tid; i < DIN; i += 256) {
        const size_t idx = base + i;
        float q = rintf(w[idx] * inv_scale);
        q = fminf(fmaxf(q, -1.0f), 1.0f);
        float v = q * scale + 0.1f * fast[idx] + 0.05f * slow[idx];
        __nv_bfloat16 h = __float2bfloat16_rn(v);
        whi[idx] = h;
        wlo[idx] = __float2bfloat16_rn(v - __bfloat162float(h));
    }
}

// ---------------------------------------------------------------------------
// bf16x3 GEMM: CTA tile 64x128, warp tile 32x32, mma.sync + ldmatrix,
// 2-stage cp.async, 2 CTAs/SM, one __syncthreads per chunk.
// MODE 0 (NT): D[m][n] = sum_k A[am+m][k]*B[bn+n][k]; epilogue writes y + relu split.
// MODE 1 (TT): D[m][n] = sum_k A[k][am+m]*B[k][bn+n]; epilogue EMA + sumsq partials.
// ---------------------------------------------------------------------------
template<int MODE>
__global__ __launch_bounds__(256, 2) void k_gemm_mma(
    const __nv_bfloat16* __restrict__ Ahi, const __nv_bfloat16* __restrict__ Alo,
    const __nv_bfloat16* __restrict__ Bhi, const __nv_bfloat16* __restrict__ Blo,
    const float* __restrict__ fast, float* __restrict__ out,
    __nv_bfloat16* __restrict__ ohi, __nv_bfloat16* __restrict__ olo)
{
    constexpr bool TRANS = (MODE == 1);
    constexpr int PITCH_A = TRANS ? 36 : 20;   // u32 per smem row of the A tiles
    constexpr int ROWS_A  = TRANS ? 32 : 64;
    constexpr int PITCH_B = TRANS ? 68 : 20;
    constexpr int ROWS_B  = TRANS ? 32 : 128;
    constexpr int TILEU_A = ROWS_A * PITCH_A;
    constexpr int TILEU_B = ROWS_B * PITCH_B;
    constexpr int OFF_B   = 2 * TILEU_A;
    constexpr int STAGEU  = 2 * TILEU_A + 2 * TILEU_B;
    constexpr size_t CH_STRIDE = TRANS ? ((size_t)BK * 4096) : (size_t)BK;

    extern __shared__ uint32_t smem[];
    __shared__ double dred[256];

    const int tid  = threadIdx.x;
    const int lane = tid & 31;
    const int wid  = tid >> 5;
    const int g    = lane >> 2;
    const int tig  = lane & 3;

    // supertile swizzle: 4 groups x (64 m-tiles x 8 n-tiles)
    const int bid   = blockIdx.x;
    const int group = bid >> 9;
    const int rem   = bid & 511;
    const int am  = (rem >> 3) * 64;                 // M tile base (64 rows)
    const int bn  = (group * 8 + (rem & 7)) * 128;   // N tile base (128 cols)

    const int wm = (wid & 1) * 32;      // warp m offset
    const int wn = (wid >> 1) * 32;     // warp n offset

    const __nv_bfloat16* const srcs[4] = {Ahi, Alo, Bhi, Blo};

    const uint32_t sm0 = smem_u32(smem);

    // ---- per-thread loader bases (6 transfers/stage: A x2, B x4) ----
    const __nv_bfloat16* src0[6];
    uint32_t dst_off[6];
    #pragma unroll
    for (int op = 0; op < 2; op++) {    // A hi/lo: 256 uint4 each
        if (!TRANS) {
            const int row = tid >> 2, q = tid & 3;
            src0[op] = srcs[op] + (size_t)(am + row) * 4096 + q * 8;
            dst_off[op] = (uint32_t)((op * TILEU_A + row * PITCH_A + q * 4) * 4);
        } else {
            const int row = tid >> 3, q = tid & 7;
            src0[op] = srcs[op] + (size_t)row * 4096 + am + q * 8;
            dst_off[op] = (uint32_t)((op * TILEU_A + row * PITCH_A + q * 4) * 4);
        }
    }
    #pragma unroll
    for (int op = 0; op < 2; op++)      // B hi/lo: 512 uint4 each
        #pragma unroll
        for (int j = 0; j < 2; j++) {
            const int i = tid + j * 256;
            const int t = 2 + op * 2 + j;
            if (!TRANS) {
                const int row = i >> 2, q = i & 3;
                src0[t] = srcs[2 + op] + (size_t)(bn + row) * 4096 + q * 8;
                dst_off[t] = (uint32_t)((OFF_B + op * TILEU_B + row * PITCH_B + q * 4) * 4);
            } else {
                const int row = i >> 4, q = i & 15;
                src0[t] = srcs[2 + op] + (size_t)row * 4096 + bn + q * 8;
                dst_off[t] = (uint32_t)((OFF_B + op * TILEU_B + row * PITCH_B + q * 4) * 4);
            }
        }

    // per-lane ldmatrix base offsets (bytes within a tile)
    uint32_t a_base, b_base;
    if (!TRANS) {
        const int ld_row = ((lane >> 3) & 1) * 8 + (lane & 7);
        const int ld_kb  = (lane >> 4) * 16;
        a_base = (uint32_t)((wm + ld_row) * 80 + ld_kb);
        b_base = (uint32_t)((wn + ld_row) * 80 + ld_kb);
    } else {
        const int ld_kr = (lane >> 4) * 8 + (lane & 7);
        const int ld_cb = ((lane >> 3) & 1) * 16;
        a_base = (uint32_t)(ld_kr * 144 + wm * 2 + ld_cb);
        b_base = (uint32_t)(ld_kr * 272 + wn * 2 + ld_cb);
    }

    float acc[2][4][4];
    #pragma unroll
    for (int mt = 0; mt < 2; mt++)
        #pragma unroll
        for (int nt = 0; nt < 4; nt++)
            #pragma unroll
            for (int r = 0; r < 4; r++) acc[mt][nt][r] = 0.f;

    #define ISSUE_STAGE(stage, chunk) do {                                          \
        const uint32_t sdst = sm0 + (uint32_t)(stage) * (STAGEU * 4);               \
        const size_t soff = (size_t)(chunk) * CH_STRIDE;                            \
        _Pragma("unroll")                                                           \
        for (int t = 0; t < 6; t++)                                                 \
            CP_ASYNC16(sdst + dst_off[t], src0[t] + soff);                          \
        CP_COMMIT();                                                                \
    } while (0)

    ISSUE_STAGE(0, 0);

    for (int c = 0; c < NCHUNK; c++) {
        const int stage_c = c & 1;
        CP_WAIT0();
        __syncthreads();
        if (c + 1 < NCHUNK) ISSUE_STAGE(stage_c ^ 1, c + 1);

        const uint32_t stg = sm0 + (uint32_t)stage_c * (STAGEU * 4);
        #pragma unroll
        for (int ks = 0; ks < 2; ks++) {
            // A fragments: [mt][term hi/lo]
            uint32_t a[2][2][4];
            #pragma unroll
            for (int mt = 0; mt < 2; mt++)
                #pragma unroll
                for (int t = 0; t < 2; t++) {
                    uint32_t addr;
                    if (!TRANS) addr = stg + t * (TILEU_A * 4) + a_base + mt * 1280 + ks * 32;
                    else        addr = stg + t * (TILEU_A * 4) + a_base + mt * 32 + ks * 2304;
                    if (!TRANS) { LDSM4(a[mt][t], addr); } else { LDSM4T(a[mt][t], addr); }
                }
            // B fragments: p in {0,1} covers nt = 2p, 2p+1
            uint32_t bh[2][4], bl[2][4];
            #pragma unroll
            for (int p = 0; p < 2; p++) {
                uint32_t addrh;
                if (!TRANS) addrh = stg + OFF_B * 4 + b_base + p * 1280 + ks * 32;
                else        addrh = stg + OFF_B * 4 + b_base + p * 32 + ks * 4352;
                const uint32_t addrl = addrh + TILEU_B * 4;
                if (!TRANS) { LDSM4(bh[p], addrh); LDSM4(bl[p], addrl); }
                else        { LDSM4T(bh[p], addrh); LDSM4T(bl[p], addrl); }
            }
            // 24 MMAs: hi*hi, hi*lo, lo*hi (acc reuse distance 8)
            #pragma unroll
            for (int p = 0; p < 2; p++) {
                uint32_t b0[2] = {bh[p][0], bh[p][2]}, b1[2] = {bh[p][1], bh[p][3]};
                mma_bf16(acc[0][2*p],   a[0][0], b0);
                mma_bf16(acc[0][2*p+1], a[0][0], b1);
                mma_bf16(acc[1][2*p],   a[1][0], b0);
                mma_bf16(acc[1][2*p+1], a[1][0], b1);
            }
            #pragma unroll
            for (int p = 0; p < 2; p++) {
                uint32_t b0[2] = {bl[p][0], bl[p][2]}, b1[2] = {bl[p][1], bl[p][3]};
                mma_bf16(acc[0][2*p],   a[0][0], b0);
                mma_bf16(acc[0][2*p+1], a[0][0], b1);
                mma_bf16(acc[1][2*p],   a[1][0], b0);
                mma_bf16(acc[1][2*p+1], a[1][0], b1);
            }
            #pragma unroll
            for (int p = 0; p < 2; p++) {
                uint32_t b0[2] = {bh[p][0], bh[p][2]}, b1[2] = {bh[p][1], bh[p][3]};
                mma_bf16(acc[0][2*p],   a[0][1], b0);
                mma_bf16(acc[0][2*p+1], a[0][1], b1);
                mma_bf16(acc[1][2*p],   a[1][1], b0);
                mma_bf16(acc[1][2*p+1], a[1][1], b1);
            }
        }
    }
    #undef ISSUE_STAGE

    // ---- epilogue ----
    double ss = 0.0;
    const float inv_tok = 1.0f / (float)TOK;
    #pragma unroll
    for (int mt = 0; mt < 2; mt++) {
        const int r0 = am + wm + mt * 16 + g;
        #pragma unroll
        for (int nt = 0; nt < 4; nt++) {
            const int col = bn + wn + nt * 8 + tig * 2;
            #pragma unroll
            for (int half = 0; half < 2; half++) {
                const int r = r0 + half * 8;
                const float d0 = acc[mt][nt][half * 2 + 0];
                const float d1 = acc[mt][nt][half * 2 + 1];
                const size_t o = (size_t)r * 4096 + col;
                if (MODE == 0) {
                    *(float2*)(out + o) = make_float2(d0, d1);
                    const float r0f = fmaxf(d0, 0.f), r1f = fmaxf(d1, 0.f);
                    union { __nv_bfloat16 b[2]; uint32_t u; } H, L;
                    H.b[0] = __float2bfloat16_rn(r0f);
                    H.b[1] = __float2bfloat16_rn(r1f);
                    L.b[0] = __float2bfloat16_rn(r0f - __bfloat162float(H.b[0]));
                    L.b[1] = __float2bfloat16_rn(r1f - __bfloat162float(H.b[1]));
                    *(uint32_t*)(ohi + o) = H.u;
                    *(uint32_t*)(olo + o) = L.u;
                } else {
                    const float2 fa = *(const float2*)(fast + o);
                    float2 v;
                    v.x = FAST_DECAY * fa.x + FAST_LR * (d0 * inv_tok);
                    v.y = FAST_DECAY * fa.y + FAST_LR * (d1 * inv_tok);
                    *(float2*)(out + o) = v;
                    ss += (double)v.x * v.x + (double)v.y * v.y;
                }
            }
        }
    }
    if (MODE == 1) {
        dred[tid] = ss;
        __syncthreads();
        #pragma unroll
        for (int off = 128; off > 0; off >>= 1) {
            if (tid < off) dred[tid] += dred[tid + off];
            __syncthreads();
        }
        if (tid == 0) g_partials[blockIdx.x] = dred[0];
    }
}

// ---------------------------------------------------------------------------
__global__ void k_norm_factor()
{
    __shared__ double red[256];
    const int tid = threadIdx.x;
    double s = 0.0;
    for (int i = tid; i < NTILES; i += 256) s += g_partials[i];
    red[tid] = s;
    __syncthreads();
    #pragma unroll
    for (int off = 128; off > 0; off >>= 1) {
        if (tid < off) red[tid] += red[tid + off];
        __syncthreads();
    }
    if (tid == 0) {
        const double norm = sqrt(red[0]);
        g_factor = (norm > HOMEO_TARGET) ? (float)(HOMEO_TARGET / (norm + 1e-6)) : 1.0f;
    }
}

__global__ __launch_bounds__(256) void k_finalize(
    const float* __restrict__ slow, float* __restrict__ fout, float* __restrict__ sout)
{
    const float fac = g_factor;
    const size_t i = (size_t)blockIdx.x * blockDim.x + threadIdx.x;
    float4 f = ((const float4*)fout)[i];
    f.x *= fac; f.y *= fac; f.z *= fac; f.w *= fac;
    ((float4*)fout)[i] = f;
    const float4 sl = ((const float4*)slow)[i];
    float4 so;
    so.x = SLOW_DECAY * sl.x + SLOW_LR * f.x;
    so.y = SLOW_DECAY * sl.y + SLOW_LR * f.y;
    so.z = SLOW_DECAY * sl.z + SLOW_LR * f.z;
    so.w = SLOW_DECAY * sl.w + SLOW_LR * f.w;
    ((float4*)sout)[i] = so;
}

// ---------------------------------------------------------------------------
extern "C" void kernel_launch(void* const* d_in, const int* in_sizes, int n_in,
                              void* d_out, int out_size)
{
    const float* x    = (const float*)d_in[0];
    const float* w    = (const float*)d_in[1];
    const float* fast = (const float*)d_in[2];
    const float* slow = (const float*)d_in[3];

    float* out   = (float*)d_out;
    float* y_out = out;
    float* f_out = out + (size_t)TOK * DOUT;
    float* s_out = f_out + ELEMS;

    __nv_bfloat16 *whi, *wlo, *xhi, *xlo, *yrhi, *yrlo;
    cudaGetSymbolAddress((void**)&whi,  g_whi);
    cudaGetSymbolAddress((void**)&wlo,  g_wlo);
    cudaGetSymbolAddress((void**)&xhi,  g_xhi);
    cudaGetSymbolAddress((void**)&xlo,  g_xlo);
    cudaGetSymbolAddress((void**)&yrhi, g_yrhi);
    cudaGetSymbolAddress((void**)&yrlo, g_yrlo);

    cudaFuncSetAttribute(k_gemm_mma<0>, cudaFuncAttributeMaxDynamicSharedMemorySize, DYN_SMEM);
    cudaFuncSetAttribute(k_gemm_mma<1>, cudaFuncAttributeMaxDynamicSharedMemorySize, DYN_SMEM);

    // 1) fused prep: w_eff quantize+split AND X split
    k_prep<<<4096 + 16384, 256>>>(w, fast, slow, x, whi, wlo, xhi, xlo);
    // 2) Y = X @ w_eff^T; epilogue emits relu(Y) bf16 hi/lo
    k_gemm_mma<0><<<NTILES, 256, DYN_SMEM>>>(xhi, xlo, whi, wlo, nullptr, y_out, yrhi, yrlo);
    // 3) new_fast (unscaled) = 0.95*fast + 0.05*(reluY^T @ X)/TOK, + partials
    k_gemm_mma<1><<<NTILES, 256, DYN_SMEM>>>(yrhi, yrlo, xhi, xlo, fast, f_out, nullptr, nullptr);
    // 4) norm -> factor
    k_norm_factor<<<1, 256>>>();
    // 5) scale fast, compute slow
    k_finalize<<<(unsigned)(ELEMS / 4 / 256), 256>>>(slow, f_out, s_out);
}

// round 10
// speedup vs baseline: 1.0567x; 1.0567x over previous
#include <cuda_runtime.h>
#include <cuda_bf16.h>
#include <stdint.h>
#include <math.h>

// ---------------------------------------------------------------------------
// Shapes (fixed)
#define TOK   4096
#define DIN   4096
#define DOUT  4096
#define ELEMS ((size_t)DOUT * (size_t)DIN)

#define FAST_DECAY 0.95f
#define FAST_LR    0.05f
#define SLOW_DECAY 0.99f
#define SLOW_LR    0.01f
#define HOMEO_TARGET 5.0

// CTA tile 128x128x32(bf16), 8 warps (4m x 2n), warp tile 32x64, 2-stage cp.async,
// split-K=2: grid = 2048 CTAs (1024 tiles x 2 K-halves) -> 6.92 waves over 296 slots.
#define BK      32
#define KCHUNKS_HALF 64              // 64 chunks per K-half
#define DYN_SMEM 81920               // 2 stages x 4 tiles x 128 x 80B -> 2 CTAs/SM
#define NRED    16384                // reduce-kernel grid (= partial count)

// ---------------------------------------------------------------------------
// Scratch
__device__ __nv_bfloat16 g_whi[ELEMS], g_wlo[ELEMS];     // w_eff split, K-major
__device__ __nv_bfloat16 g_xhi[ELEMS], g_xlo[ELEMS];     // X split [TOK, DIN]
__device__ __nv_bfloat16 g_yrhi[ELEMS], g_yrlo[ELEMS];   // relu(Y) split [TOK, DOUT]
__device__ float  g_p0[ELEMS];                           // split-K partial, kh=0
__device__ float  g_p1[ELEMS];                           // split-K partial, kh=1
__device__ double g_partials[NRED];
__device__ float  g_factor;

// ---------------------------------------------------------------------------
__device__ __forceinline__ uint32_t smem_u32(const void* p) {
    uint32_t a;
    asm("{ .reg .u64 t; cvta.to.shared.u64 t, %1; cvt.u32.u64 %0, t; }" : "=r"(a) : "l"(p));
    return a;
}
__device__ __forceinline__ void mma_bf16(float* c, const uint32_t* a, const uint32_t* b) {
    asm volatile(
        "mma.sync.aligned.m16n8k16.row.col.f32.bf16.bf16.f32 "
        "{%0,%1,%2,%3}, {%4,%5,%6,%7}, {%8,%9}, {%0,%1,%2,%3};"
        : "+f"(c[0]), "+f"(c[1]), "+f"(c[2]), "+f"(c[3])
        : "r"(a[0]), "r"(a[1]), "r"(a[2]), "r"(a[3]), "r"(b[0]), "r"(b[1]));
}
#define LDSM4(R, A) \
    asm volatile("ldmatrix.sync.aligned.m8n8.x4.shared.b16 {%0,%1,%2,%3}, [%4];" \
        : "=r"((R)[0]), "=r"((R)[1]), "=r"((R)[2]), "=r"((R)[3]) : "r"(A))
#define LDSM4T(R, A) \
    asm volatile("ldmatrix.sync.aligned.m8n8.x4.trans.shared.b16 {%0,%1,%2,%3}, [%4];" \
        : "=r"((R)[0]), "=r"((R)[1]), "=r"((R)[2]), "=r"((R)[3]) : "r"(A))
#define CP_ASYNC16(dst, src) \
    asm volatile("cp.async.cg.shared.global [%0], [%1], 16;" :: "r"(dst), "l"(src))
#define CP_COMMIT() asm volatile("cp.async.commit_group;" ::: "memory")
#define CP_WAIT0()  asm volatile("cp.async.wait_group 0;" ::: "memory")

// ---------------------------------------------------------------------------
// Fused prep: blocks [0,4096): per-row quantize+combine w_eff -> whi/wlo
//             blocks [4096,20480): elementwise split X -> xhi/xlo
__global__ __launch_bounds__(256) void k_prep(
    const float* __restrict__ w, const float* __restrict__ fast, const float* __restrict__ slow,
    const float* __restrict__ x,
    __nv_bfloat16* __restrict__ whi, __nv_bfloat16* __restrict__ wlo,
    __nv_bfloat16* __restrict__ xhi, __nv_bfloat16* __restrict__ xlo)
{
    const int tid = threadIdx.x;
    if (blockIdx.x >= 4096) {
        const size_t i = ((size_t)(blockIdx.x - 4096) * 256 + tid) * 4;
        float4 v = *(const float4*)(x + i);
        union { __nv_bfloat16 b[4]; uint64_t u; } H, L;
        float f[4] = {v.x, v.y, v.z, v.w};
        #pragma unroll
        for (int j = 0; j < 4; j++) {
            __nv_bfloat16 h = __float2bfloat16_rn(f[j]);
            H.b[j] = h;
            L.b[j] = __float2bfloat16_rn(f[j] - __bfloat162float(h));
        }
        *(uint64_t*)(xhi + i) = H.u;
        *(uint64_t*)(xlo + i) = L.u;
        return;
    }
    const int row = blockIdx.x;
    const size_t base = (size_t)row * DIN;

    float s = 0.f;
    for (int i = tid; i < DIN; i += 256) s += fabsf(w[base + i]);
    __shared__ float red[256];
    red[tid] = s;
    __syncthreads();
    #pragma unroll
    for (int off = 128; off > 0; off >>= 1) {
        if (tid < off) red[tid] += red[tid + off];
        __syncthreads();
    }
    float scale = fmaxf(red[0] * (1.0f / (float)DIN), 1e-5f);
    const float inv_scale = 1.0f / scale;

    for (int i = tid; i < DIN; i += 256) {
        const size_t idx = base + i;
        float q = rintf(w[idx] * inv_scale);
        q = fminf(fmaxf(q, -1.0f), 1.0f);
        float v = q * scale + 0.1f * fast[idx] + 0.05f * slow[idx];
        __nv_bfloat16 h = __float2bfloat16_rn(v);
        whi[idx] = h;
        wlo[idx] = __float2bfloat16_rn(v - __bfloat162float(h));
    }
}

// ---------------------------------------------------------------------------
// bf16x3 GEMM, split-K=2: CTA tile 128x128, each CTA does one K-half (64 chunks).
// Writes fp32 partials to p0 (kh=0) or p1 (kh=1).
// MODE 0 (NT): A,B row-major K-contiguous. MODE 1 (TT): k-major via ldmatrix.trans.
// ---------------------------------------------------------------------------
template<int MODE>
__global__ __launch_bounds__(256, 2) void k_gemm_sk(
    const __nv_bfloat16* __restrict__ Ahi, const __nv_bfloat16* __restrict__ Alo,
    const __nv_bfloat16* __restrict__ Bhi, const __nv_bfloat16* __restrict__ Blo,
    float* __restrict__ p0, float* __restrict__ p1)
{
    constexpr bool TRANS = (MODE == 1);
    constexpr int PITCH = TRANS ? 68 : 20;           // u32 per smem row
    constexpr int ROWS  = TRANS ? 32 : 128;
    constexpr int TILEU = ROWS * PITCH;
    constexpr int STAGEU = 4 * TILEU;
    constexpr size_t CH_STRIDE = TRANS ? ((size_t)BK * 4096) : (size_t)BK;

    extern __shared__ uint32_t smem[];

    const int tid  = threadIdx.x;
    const int lane = tid & 31;
    const int wid  = tid >> 5;
    const int g    = lane >> 2;
    const int tig  = lane & 3;

    // bid -> (K-half, tile); supertile swizzle on tile: 4 groups x (32m x 8n)
    const int bid = blockIdx.x;
    const int kh  = bid >> 10;            // 0 or 1
    const int t   = bid & 1023;
    const int group = t >> 8;
    const int rem   = t & 255;
    const int am  = (rem >> 3) * 128;
    const int bn  = (group * 8 + (rem & 7)) * 128;
    const int c0  = kh * KCHUNKS_HALF;    // first chunk of this CTA's K-half
    float* __restrict__ pout = kh ? p1 : p0;

    const int wm = (wid & 3) * 32;
    const int wn = (wid >> 2) * 64;

    const __nv_bfloat16* const srcs[4] = {Ahi, Alo, Bhi, Blo};
    const int cbase[4] = {am, am, bn, bn};

    const uint32_t sm0 = smem_u32(smem);

    // ---- per-thread loader bases (8 transfers/stage: 4 ops x 2) ----
    const __nv_bfloat16* src0[8];
    uint32_t dst_off[8];
    #pragma unroll
    for (int op = 0; op < 4; op++)
        #pragma unroll
        for (int j = 0; j < 2; j++) {
            const int i = tid + j * 256;
            const int row = TRANS ? (i >> 4) : (i >> 2);
            const int q   = TRANS ? (i & 15) : (i & 3);
            if (!TRANS)
                src0[op * 2 + j] = srcs[op] + (size_t)(cbase[op] + row) * 4096 + q * 8;
            else
                src0[op * 2 + j] = srcs[op] + (size_t)row * 4096 + cbase[op] + q * 8;
            dst_off[op * 2 + j] = (uint32_t)((op * TILEU + row * PITCH + q * 4) * 4);
        }

    // per-lane ldmatrix base offsets (bytes within a tile)
    uint32_t a_base, b_base;
    if (!TRANS) {
        const int ld_row = ((lane >> 3) & 1) * 8 + (lane & 7);
        const int ld_kb  = (lane >> 4) * 16;
        a_base = (uint32_t)((wm + ld_row) * 80 + ld_kb);
        b_base = (uint32_t)((wn + ld_row) * 80 + ld_kb);
    } else {
        const int ld_kr = (lane >> 4) * 8 + (lane & 7);
        const int ld_cb = ((lane >> 3) & 1) * 16;
        a_base = (uint32_t)(ld_kr * 272 + wm * 2 + ld_cb);
        b_base = (uint32_t)(ld_kr * 272 + wn * 2 + ld_cb);
    }

    float acc[2][8][4];
    #pragma unroll
    for (int mt = 0; mt < 2; mt++)
        #pragma unroll
        for (int nt = 0; nt < 8; nt++)
            #pragma unroll
            for (int r = 0; r < 4; r++) acc[mt][nt][r] = 0.f;

    #define ISSUE_STAGE(stage, chunk) do {                                          \
        const uint32_t sdst = sm0 + (uint32_t)(stage) * (STAGEU * 4);               \
        const size_t soff = (size_t)(chunk) * CH_STRIDE;                            \
        _Pragma("unroll")                                                           \
        for (int tt = 0; tt < 8; tt++)                                              \
            CP_ASYNC16(sdst + dst_off[tt], src0[tt] + soff);                        \
        CP_COMMIT();                                                                \
    } while (0)

    ISSUE_STAGE(0, c0);

    for (int cl = 0; cl < KCHUNKS_HALF; cl++) {
        const int stage_c = cl & 1;
        CP_WAIT0();
        __syncthreads();
        if (cl + 1 < KCHUNKS_HALF) ISSUE_STAGE(stage_c ^ 1, c0 + cl + 1);

        const uint32_t stg = sm0 + (uint32_t)stage_c * (STAGEU * 4);
        #pragma unroll
        for (int ks = 0; ks < 2; ks++) {
            uint32_t a[2][2][4];
            #pragma unroll
            for (int mt = 0; mt < 2; mt++)
                #pragma unroll
                for (int tt = 0; tt < 2; tt++) {
                    uint32_t addr;
                    if (!TRANS) addr = stg + tt * (TILEU * 4) + a_base + mt * 1280 + ks * 32;
                    else        addr = stg + tt * (TILEU * 4) + a_base + mt * 32 + ks * 4352;
                    if (!TRANS) { LDSM4(a[mt][tt], addr); } else { LDSM4T(a[mt][tt], addr); }
                }
            #pragma unroll
            for (int pp = 0; pp < 2; pp++) {
                uint32_t bh[2][4], bl[2][4];
                #pragma unroll
                for (int q = 0; q < 2; q++) {
                    const int p = pp * 2 + q;
                    if (!TRANS) {
                        LDSM4(bh[q], stg + 2 * (TILEU * 4) + b_base + p * 1280 + ks * 32);
                        LDSM4(bl[q], stg + 3 * (TILEU * 4) + b_base + p * 1280 + ks * 32);
                    } else {
                        LDSM4T(bh[q], stg + 2 * (TILEU * 4) + b_base + p * 32 + ks * 4352);
                        LDSM4T(bl[q], stg + 3 * (TILEU * 4) + b_base + p * 32 + ks * 4352);
                    }
                }
                #pragma unroll
                for (int q = 0; q < 2; q++) {
                    const int p = pp * 2 + q;
                    uint32_t b0[2] = {bh[q][0], bh[q][2]}, b1[2] = {bh[q][1], bh[q][3]};
                    mma_bf16(acc[0][2*p],   a[0][0], b0);
                    mma_bf16(acc[0][2*p+1], a[0][0], b1);
                    mma_bf16(acc[1][2*p],   a[1][0], b0);
                    mma_bf16(acc[1][2*p+1], a[1][0], b1);
                }
                #pragma unroll
                for (int q = 0; q < 2; q++) {
                    const int p = pp * 2 + q;
                    uint32_t b0[2] = {bl[q][0], bl[q][2]}, b1[2] = {bl[q][1], bl[q][3]};
                    mma_bf16(acc[0][2*p],   a[0][0], b0);
                    mma_bf16(acc[0][2*p+1], a[0][0], b1);
                    mma_bf16(acc[1][2*p],   a[1][0], b0);
                    mma_bf16(acc[1][2*p+1], a[1][0], b1);
                }
                #pragma unroll
                for (int q = 0; q < 2; q++) {
                    const int p = pp * 2 + q;
                    uint32_t b0[2] = {bh[q][0], bh[q][2]}, b1[2] = {bh[q][1], bh[q][3]};
                    mma_bf16(acc[0][2*p],   a[0][1], b0);
                    mma_bf16(acc[0][2*p+1], a[0][1], b1);
                    mma_bf16(acc[1][2*p],   a[1][1], b0);
                    mma_bf16(acc[1][2*p+1], a[1][1], b1);
                }
            }
        }
    }
    #undef ISSUE_STAGE

    // ---- epilogue: write fp32 partials ----
    #pragma unroll
    for (int mt = 0; mt < 2; mt++) {
        const int r0 = am + wm + mt * 16 + g;
        #pragma unroll
        for (int nt = 0; nt < 8; nt++) {
            const int col = bn + wn + nt * 8 + tig * 2;
            #pragma unroll
            for (int half = 0; half < 2; half++) {
                const int r = r0 + half * 8;
                const size_t o = (size_t)r * 4096 + col;
                *(float2*)(pout + o) =
                    make_float2(acc[mt][nt][half * 2 + 0], acc[mt][nt][half * 2 + 1]);
            }
        }
    }
}

// ---------------------------------------------------------------------------
// Reduce 1: y = p0 + p1; write y fp32 and relu-split bf16 hi/lo for GEMM2's A.
__global__ __launch_bounds__(256) void k_reduce_y(
    const float* __restrict__ p0, const float* __restrict__ p1,
    float* __restrict__ y, __nv_bfloat16* __restrict__ yrhi, __nv_bfloat16* __restrict__ yrlo)
{
    const size_t i = ((size_t)blockIdx.x * 256 + threadIdx.x) * 4;
    const float4 a = *(const float4*)(p0 + i);
    const float4 b = *(const float4*)(p1 + i);
    float4 s = make_float4(a.x + b.x, a.y + b.y, a.z + b.z, a.w + b.w);
    *(float4*)(y + i) = s;
    union { __nv_bfloat16 b[4]; uint64_t u; } H, L;
    float f[4] = {fmaxf(s.x, 0.f), fmaxf(s.y, 0.f), fmaxf(s.z, 0.f), fmaxf(s.w, 0.f)};
    #pragma unroll
    for (int j = 0; j < 4; j++) {
        __nv_bfloat16 h = __float2bfloat16_rn(f[j]);
        H.b[j] = h;
        L.b[j] = __float2bfloat16_rn(f[j] - __bfloat162float(h));
    }
    *(uint64_t*)(yrhi + i) = H.u;
    *(uint64_t*)(yrlo + i) = L.u;
}

// ---------------------------------------------------------------------------
// Reduce 2: d = p0 + p1; new_fast(unscaled) = 0.95*fast + 0.05*d/TOK; sumsq partials.
__global__ __launch_bounds__(256) void k_reduce_f(
    const float* __restrict__ p0, const float* __restrict__ p1,
    const float* __restrict__ fast, float* __restrict__ fout)
{
    __shared__ double dred[256];
    const int tid = threadIdx.x;
    const size_t i = ((size_t)blockIdx.x * 256 + tid) * 4;
    const float4 a = *(const float4*)(p0 + i);
    const float4 b = *(const float4*)(p1 + i);
    const float4 fa = *(const float4*)(fast + i);
    const float inv_tok = 1.0f / (float)TOK;
    float4 v;
    v.x = FAST_DECAY * fa.x + FAST_LR * ((a.x + b.x) * inv_tok);
    v.y = FAST_DECAY * fa.y + FAST_LR * ((a.y + b.y) * inv_tok);
    v.z = FAST_DECAY * fa.z + FAST_LR * ((a.z + b.z) * inv_tok);
    v.w = FAST_DECAY * fa.w + FAST_LR * ((a.w + b.w) * inv_tok);
    *(float4*)(fout + i) = v;
    double ss = (double)v.x * v.x + (double)v.y * v.y
              + (double)v.z * v.z + (double)v.w * v.w;
    dred[tid] = ss;
    __syncthreads();
    #pragma unroll
    for (int off = 128; off > 0; off >>= 1) {
        if (tid < off) dred[tid] += dred[tid + off];
        __syncthreads();
    }
    if (tid == 0) g_partials[blockIdx.x] = dred[0];
}

// ---------------------------------------------------------------------------
__global__ void k_norm_factor()
{
    __shared__ double red[256];
    const int tid = threadIdx.x;
    double s = 0.0;
    for (int i = tid; i < NRED; i += 256) s += g_partials[i];
    red[tid] = s;
    __syncthreads();
    #pragma unroll
    for (int off = 128; off > 0; off >>= 1) {
        if (tid < off) red[tid] += red[tid + off];
        __syncthreads();
    }
    if (tid == 0) {
        const double norm = sqrt(red[0]);
        g_factor = (norm > HOMEO_TARGET) ? (float)(HOMEO_TARGET / (norm + 1e-6)) : 1.0f;
    }
}

__global__ __launch_bounds__(256) void k_finalize(
    const float* __restrict__ slow, float* __restrict__ fout, float* __restrict__ sout)
{
    const float fac = g_factor;
    const size_t i = (size_t)blockIdx.x * blockDim.x + threadIdx.x;
    float4 f = ((const float4*)fout)[i];
    f.x *= fac; f.y *= fac; f.z *= fac; f.w *= fac;
    ((float4*)fout)[i] = f;
    const float4 sl = ((const float4*)slow)[i];
    float4 so;
    so.x = SLOW_DECAY * sl.x + SLOW_LR * f.x;
    so.y = SLOW_DECAY * sl.y + SLOW_LR * f.y;
    so.z = SLOW_DECAY * sl.z + SLOW_LR * f.z;
    so.w = SLOW_DECAY * sl.w + SLOW_LR * f.w;
    ((float4*)sout)[i] = so;
}

// ---------------------------------------------------------------------------
extern "C" void kernel_launch(void* const* d_in, const int* in_sizes, int n_in,
                              void* d_out, int out_size)
{
    const float* x    = (const float*)d_in[0];
    const float* w    = (const float*)d_in[1];
    const float* fast = (const float*)d_in[2];
    const float* slow = (const float*)d_in[3];

    float* out   = (float*)d_out;
    float* y_out = out;
    float* f_out = out + (size_t)TOK * DOUT;
    float* s_out = f_out + ELEMS;

    __nv_bfloat16 *whi, *wlo, *xhi, *xlo, *yrhi, *yrlo;
    float *p0, *p1;
    cudaGetSymbolAddress((void**)&whi,  g_whi);
    cudaGetSymbolAddress((void**)&wlo,  g_wlo);
    cudaGetSymbolAddress((void**)&xhi,  g_xhi);
    cudaGetSymbolAddress((void**)&xlo,  g_xlo);
    cudaGetSymbolAddress((void**)&yrhi, g_yrhi);
    cudaGetSymbolAddress((void**)&yrlo, g_yrlo);
    cudaGetSymbolAddress((void**)&p0,   g_p0);
    cudaGetSymbolAddress((void**)&p1,   g_p1);

    cudaFuncSetAttribute(k_gemm_sk<0>, cudaFuncAttributeMaxDynamicSharedMemorySize, DYN_SMEM);
    cudaFuncSetAttribute(k_gemm_sk<1>, cudaFuncAttributeMaxDynamicSharedMemorySize, DYN_SMEM);

    // 1) fused prep: w_eff quantize+split AND X split
    k_prep<<<4096 + 16384, 256>>>(w, fast, slow, x, whi, wlo, xhi, xlo);
    // 2) GEMM1 split-K partials: p0/p1 = X @ w_eff^T (K halves)
    k_gemm_sk<0><<<2048, 256, DYN_SMEM>>>(xhi, xlo, whi, wlo, p0, p1);
    // 3) reduce -> y, relu-split bf16
    k_reduce_y<<<NRED, 256>>>(p0, p1, y_out, yrhi, yrlo);
    // 4) GEMM2 split-K partials: p0/p1 = reluY^T @ X (K halves)
    k_gemm_sk<1><<<2048, 256, DYN_SMEM>>>(yrhi, yrlo, xhi, xlo, p0, p1);
    // 5) reduce -> new_fast (unscaled) + sumsq partials
    k_reduce_f<<<NRED, 256>>>(p0, p1, fast, f_out);
    // 6) norm -> factor
    k_norm_factor<<<1, 256>>>();
    // 7) scale fast, compute slow
    k_finalize<<<(unsigned)(ELEMS / 4 / 256), 256>>>(slow, f_out, s_out);
}

// round 11
// speedup vs baseline: 1.1079x; 1.0485x over previous
#include <cuda_runtime.h>
#include <cuda_bf16.h>
#include <stdint.h>
#include <math.h>

// ---------------------------------------------------------------------------
// Shapes (fixed)
#define TOK   4096
#define DIN   4096
#define DOUT  4096
#define ELEMS ((size_t)DOUT * (size_t)DIN)

#define FAST_DECAY 0.95f
#define FAST_LR    0.05f
#define SLOW_DECAY 0.99f
#define SLOW_LR    0.01f
#define HOMEO_TARGET 5.0

// CTA tile 128x128x32(bf16), 8 warps (4m x 2n), warp tile 32x64, 2-stage cp.async,
// persistent CTAs: grid = 296 (148 SMs x 2), tiles claimed via atomic counter.
#define BK      32
#define NCHUNK  (4096 / BK)          // 128
#define NTILES  1024
#define NPERSIST 296
#define DYN_SMEM 81920               // 2 stages x 4 tiles x 128 x 80B -> 2 CTAs/SM

// ---------------------------------------------------------------------------
// Scratch
__device__ __nv_bfloat16 g_whi[ELEMS], g_wlo[ELEMS];     // w_eff split, K-major
__device__ __nv_bfloat16 g_xhi[ELEMS], g_xlo[ELEMS];     // X split [TOK, DIN]
__device__ __nv_bfloat16 g_yrhi[ELEMS], g_yrlo[ELEMS];   // relu(Y) split [TOK, DOUT]
__device__ double g_partials[NTILES];
__device__ float  g_factor;
__device__ unsigned g_ctr0, g_ctr1;                      // persistent tile counters

// ---------------------------------------------------------------------------
__device__ __forceinline__ uint32_t smem_u32(const void* p) {
    uint32_t a;
    asm("{ .reg .u64 t; cvta.to.shared.u64 t, %1; cvt.u32.u64 %0, t; }" : "=r"(a) : "l"(p));
    return a;
}
__device__ __forceinline__ void mma_bf16(float* c, const uint32_t* a, const uint32_t* b) {
    asm volatile(
        "mma.sync.aligned.m16n8k16.row.col.f32.bf16.bf16.f32 "
        "{%0,%1,%2,%3}, {%4,%5,%6,%7}, {%8,%9}, {%0,%1,%2,%3};"
        : "+f"(c[0]), "+f"(c[1]), "+f"(c[2]), "+f"(c[3])
        : "r"(a[0]), "r"(a[1]), "r"(a[2]), "r"(a[3]), "r"(b[0]), "r"(b[1]));
}
#define LDSM4(R, A) \
    asm volatile("ldmatrix.sync.aligned.m8n8.x4.shared.b16 {%0,%1,%2,%3}, [%4];" \
        : "=r"((R)[0]), "=r"((R)[1]), "=r"((R)[2]), "=r"((R)[3]) : "r"(A))
#define LDSM4T(R, A) \
    asm volatile("ldmatrix.sync.aligned.m8n8.x4.trans.shared.b16 {%0,%1,%2,%3}, [%4];" \
        : "=r"((R)[0]), "=r"((R)[1]), "=r"((R)[2]), "=r"((R)[3]) : "r"(A))
#define CP_ASYNC16(dst, src) \
    asm volatile("cp.async.cg.shared.global [%0], [%1], 16;" :: "r"(dst), "l"(src))
#define CP_COMMIT() asm volatile("cp.async.commit_group;" ::: "memory")
#define CP_WAIT0()  asm volatile("cp.async.wait_group 0;" ::: "memory")

// ---------------------------------------------------------------------------
// Fused prep: blocks [0,4096): per-row quantize+combine w_eff -> whi/wlo
//             blocks [4096,20480): elementwise split X -> xhi/xlo
// Block 0 also resets the persistent tile counters (every launch -> replay-safe).
__global__ __launch_bounds__(256) void k_prep(
    const float* __restrict__ w, const float* __restrict__ fast, const float* __restrict__ slow,
    const float* __restrict__ x,
    __nv_bfloat16* __restrict__ whi, __nv_bfloat16* __restrict__ wlo,
    __nv_bfloat16* __restrict__ xhi, __nv_bfloat16* __restrict__ xlo)
{
    const int tid = threadIdx.x;
    if (blockIdx.x == 0 && tid == 0) { g_ctr0 = 0u; g_ctr1 = 0u; }
    if (blockIdx.x >= 4096) {
        const size_t i = ((size_t)(blockIdx.x - 4096) * 256 + tid) * 4;
        float4 v = *(const float4*)(x + i);
        union { __nv_bfloat16 b[4]; uint64_t u; } H, L;
        float f[4] = {v.x, v.y, v.z, v.w};
        #pragma unroll
        for (int j = 0; j < 4; j++) {
            __nv_bfloat16 h = __float2bfloat16_rn(f[j]);
            H.b[j] = h;
            L.b[j] = __float2bfloat16_rn(f[j] - __bfloat162float(h));
        }
        *(uint64_t*)(xhi + i) = H.u;
        *(uint64_t*)(xlo + i) = L.u;
        return;
    }
    const int row = blockIdx.x;
    const size_t base = (size_t)row * DIN;

    float s = 0.f;
    for (int i = tid; i < DIN; i += 256) s += fabsf(w[base + i]);
    __shared__ float red[256];
    red[tid] = s;
    __syncthreads();
    #pragma unroll
    for (int off = 128; off > 0; off >>= 1) {
        if (tid < off) red[tid] += red[tid + off];
        __syncthreads();
    }
    float scale = fmaxf(red[0] * (1.0f / (float)DIN), 1e-5f);
    const float inv_scale = 1.0f / scale;

    for (int i = tid; i < DIN; i += 256) {
        const size_t idx = base + i;
        float q = rintf(w[idx] * inv_scale);
        q = fminf(fmaxf(q, -1.0f), 1.0f);
        float v = q * scale + 0.1f * fast[idx] + 0.05f * slow[idx];
        __nv_bfloat16 h = __float2bfloat16_rn(v);
        whi[idx] = h;
        wlo[idx] = __float2bfloat16_rn(v - __bfloat162float(h));
    }
}

// ---------------------------------------------------------------------------
// Persistent bf16x3 GEMM: CTA tile 128x128, warp tile 32x64, mma.sync + ldmatrix,
// 2-stage cp.async, 2 CTAs/SM, tiles claimed from an atomic counter.
// MODE 0 (NT): D[m][n] = sum_k A[am+m][k]*B[bn+n][k]; epilogue writes y + relu split.
// MODE 1 (TT): D[m][n] = sum_k A[k][am+m]*B[k][bn+n]; epilogue EMA + sumsq partials.
// Deterministic: each tile's result is independent of which CTA computes it.
// ---------------------------------------------------------------------------
template<int MODE>
__global__ __launch_bounds__(256, 2) void k_gemm_mma(
    const __nv_bfloat16* __restrict__ Ahi, const __nv_bfloat16* __restrict__ Alo,
    const __nv_bfloat16* __restrict__ Bhi, const __nv_bfloat16* __restrict__ Blo,
    const float* __restrict__ fast, float* __restrict__ out,
    __nv_bfloat16* __restrict__ ohi, __nv_bfloat16* __restrict__ olo)
{
    constexpr bool TRANS = (MODE == 1);
    constexpr int PITCH = TRANS ? 68 : 20;           // u32 per smem row
    constexpr int ROWS  = TRANS ? 32 : 128;
    constexpr int TILEU = ROWS * PITCH;
    constexpr int STAGEU = 4 * TILEU;
    constexpr size_t CH_STRIDE = TRANS ? ((size_t)BK * 4096) : (size_t)BK;

    extern __shared__ uint32_t smem[];
    __shared__ double dred[256];
    __shared__ unsigned s_tile;

    const int tid  = threadIdx.x;
    const int lane = tid & 31;
    const int wid  = tid >> 5;
    const int g    = lane >> 2;
    const int tig  = lane & 3;

    const int wm = (wid & 3) * 32;
    const int wn = (wid >> 2) * 64;

    const __nv_bfloat16* const srcs[4] = {Ahi, Alo, Bhi, Blo};
    const uint32_t sm0 = smem_u32(smem);

    // per-thread loader geometry (tile-independent parts)
    int l_row[4], l_q[4];
    uint32_t dst_off[8];
    #pragma unroll
    for (int op = 0; op < 4; op++)
        #pragma unroll
        for (int j = 0; j < 2; j++) {
            const int i = tid + j * 256;
            const int row = TRANS ? (i >> 4) : (i >> 2);
            const int q   = TRANS ? (i & 15) : (i & 3);
            if (j == 0) { l_row[op] = row; l_q[op] = q; }
            dst_off[op * 2 + j] = (uint32_t)((op * TILEU + row * PITCH + q * 4) * 4);
        }
    (void)l_row; (void)l_q;

    // per-lane ldmatrix base offsets (bytes within a tile)
    uint32_t a_base, b_base;
    if (!TRANS) {
        const int ld_row = ((lane >> 3) & 1) * 8 + (lane & 7);
        const int ld_kb  = (lane >> 4) * 16;
        a_base = (uint32_t)((wm + ld_row) * 80 + ld_kb);
        b_base = (uint32_t)((wn + ld_row) * 80 + ld_kb);
    } else {
        const int ld_kr = (lane >> 4) * 8 + (lane & 7);
        const int ld_cb = ((lane >> 3) & 1) * 16;
        a_base = (uint32_t)(ld_kr * 272 + wm * 2 + ld_cb);
        b_base = (uint32_t)(ld_kr * 272 + wn * 2 + ld_cb);
    }

    for (;;) {
        // ---- claim a tile ----
        if (tid == 0)
            s_tile = atomicAdd(TRANS ? &g_ctr1 : &g_ctr0, 1u);
        __syncthreads();
        const unsigned t = s_tile;
        if (t >= NTILES) break;

        // supertile swizzle: 4 groups x (32 m-tiles x 8 n-tiles)
        const int group = (int)(t >> 8);
        const int rem   = (int)(t & 255);
        const int am  = (rem >> 3) * 128;
        const int bn  = (group * 8 + (rem & 7)) * 128;
        const int cbase[4] = {am, am, bn, bn};

        // per-tile loader source pointers
        const __nv_bfloat16* src0[8];
        #pragma unroll
        for (int op = 0; op < 4; op++)
            #pragma unroll
            for (int j = 0; j < 2; j++) {
                const int i = tid + j * 256;
                const int row = TRANS ? (i >> 4) : (i >> 2);
                const int q   = TRANS ? (i & 15) : (i & 3);
                if (!TRANS)
                    src0[op * 2 + j] = srcs[op] + (size_t)(cbase[op] + row) * 4096 + q * 8;
                else
                    src0[op * 2 + j] = srcs[op] + (size_t)row * 4096 + cbase[op] + q * 8;
            }

        float acc[2][8][4];
        #pragma unroll
        for (int mt = 0; mt < 2; mt++)
            #pragma unroll
            for (int nt = 0; nt < 8; nt++)
                #pragma unroll
                for (int r = 0; r < 4; r++) acc[mt][nt][r] = 0.f;

        #define ISSUE_STAGE(stage, chunk) do {                                      \
            const uint32_t sdst = sm0 + (uint32_t)(stage) * (STAGEU * 4);           \
            const size_t soff = (size_t)(chunk) * CH_STRIDE;                        \
            _Pragma("unroll")                                                       \
            for (int tt = 0; tt < 8; tt++)                                          \
                CP_ASYNC16(sdst + dst_off[tt], src0[tt] + soff);                    \
            CP_COMMIT();                                                            \
        } while (0)

        ISSUE_STAGE(0, 0);

        for (int c = 0; c < NCHUNK; c++) {
            const int stage_c = c & 1;
            CP_WAIT0();
            __syncthreads();
            if (c + 1 < NCHUNK) ISSUE_STAGE(stage_c ^ 1, c + 1);

            const uint32_t stg = sm0 + (uint32_t)stage_c * (STAGEU * 4);
            #pragma unroll
            for (int ks = 0; ks < 2; ks++) {
                uint32_t a[2][2][4];
                #pragma unroll
                for (int mt = 0; mt < 2; mt++)
                    #pragma unroll
                    for (int tt = 0; tt < 2; tt++) {
                        uint32_t addr;
                        if (!TRANS) addr = stg + tt * (TILEU * 4) + a_base + mt * 1280 + ks * 32;
                        else        addr = stg + tt * (TILEU * 4) + a_base + mt * 32 + ks * 4352;
                        if (!TRANS) { LDSM4(a[mt][tt], addr); } else { LDSM4T(a[mt][tt], addr); }
                    }
                #pragma unroll
                for (int pp = 0; pp < 2; pp++) {
                    uint32_t bh[2][4], bl[2][4];
                    #pragma unroll
                    for (int q = 0; q < 2; q++) {
                        const int p = pp * 2 + q;
                        if (!TRANS) {
                            LDSM4(bh[q], stg + 2 * (TILEU * 4) + b_base + p * 1280 + ks * 32);
                            LDSM4(bl[q], stg + 3 * (TILEU * 4) + b_base + p * 1280 + ks * 32);
                        } else {
                            LDSM4T(bh[q], stg + 2 * (TILEU * 4) + b_base + p * 32 + ks * 4352);
                            LDSM4T(bl[q], stg + 3 * (TILEU * 4) + b_base + p * 32 + ks * 4352);
                        }
                    }
                    #pragma unroll
                    for (int q = 0; q < 2; q++) {
                        const int p = pp * 2 + q;
                        uint32_t b0[2] = {bh[q][0], bh[q][2]}, b1[2] = {bh[q][1], bh[q][3]};
                        mma_bf16(acc[0][2*p],   a[0][0], b0);
                        mma_bf16(acc[0][2*p+1], a[0][0], b1);
                        mma_bf16(acc[1][2*p],   a[1][0], b0);
                        mma_bf16(acc[1][2*p+1], a[1][0], b1);
                    }
                    #pragma unroll
                    for (int q = 0; q < 2; q++) {
                        const int p = pp * 2 + q;
                        uint32_t b0[2] = {bl[q][0], bl[q][2]}, b1[2] = {bl[q][1], bl[q][3]};
                        mma_bf16(acc[0][2*p],   a[0][0], b0);
                        mma_bf16(acc[0][2*p+1], a[0][0], b1);
                        mma_bf16(acc[1][2*p],   a[1][0], b0);
                        mma_bf16(acc[1][2*p+1], a[1][0], b1);
                    }
                    #pragma unroll
                    for (int q = 0; q < 2; q++) {
                        const int p = pp * 2 + q;
                        uint32_t b0[2] = {bh[q][0], bh[q][2]}, b1[2] = {bh[q][1], bh[q][3]};
                        mma_bf16(acc[0][2*p],   a[0][1], b0);
                        mma_bf16(acc[0][2*p+1], a[0][1], b1);
                        mma_bf16(acc[1][2*p],   a[1][1], b0);
                        mma_bf16(acc[1][2*p+1], a[1][1], b1);
                    }
                }
            }
        }
        #undef ISSUE_STAGE

        // ---- epilogue ----
        double ss = 0.0;
        const float inv_tok = 1.0f / (float)TOK;
        #pragma unroll
        for (int mt = 0; mt < 2; mt++) {
            const int r0 = am + wm + mt * 16 + g;
            #pragma unroll
            for (int nt = 0; nt < 8; nt++) {
                const int col = bn + wn + nt * 8 + tig * 2;
                #pragma unroll
                for (int half = 0; half < 2; half++) {
                    const int r = r0 + half * 8;
                    const float d0 = acc[mt][nt][half * 2 + 0];
                    const float d1 = acc[mt][nt][half * 2 + 1];
                    const size_t o = (size_t)r * 4096 + col;
                    if (MODE == 0) {
                        *(float2*)(out + o) = make_float2(d0, d1);
                        const float r0f = fmaxf(d0, 0.f), r1f = fmaxf(d1, 0.f);
                        union { __nv_bfloat16 b[2]; uint32_t u; } H, L;
                        H.b[0] = __float2bfloat16_rn(r0f);
                        H.b[1] = __float2bfloat16_rn(r1f);
                        L.b[0] = __float2bfloat16_rn(r0f - __bfloat162float(H.b[0]));
                        L.b[1] = __float2bfloat16_rn(r1f - __bfloat162float(H.b[1]));
                        *(uint32_t*)(ohi + o) = H.u;
                        *(uint32_t*)(olo + o) = L.u;
                    } else {
                        const float2 fa = *(const float2*)(fast + o);
                        float2 v;
                        v.x = FAST_DECAY * fa.x + FAST_LR * (d0 * inv_tok);
                        v.y = FAST_DECAY * fa.y + FAST_LR * (d1 * inv_tok);
                        *(float2*)(out + o) = v;
                        ss += (double)v.x * v.x + (double)v.y * v.y;
                    }
                }
            }
        }
        if (MODE == 1) {
            dred[tid] = ss;
            __syncthreads();
            #pragma unroll
            for (int off = 128; off > 0; off >>= 1) {
                if (tid < off) dred[tid] += dred[tid + off];
                __syncthreads();
            }
            if (tid == 0) g_partials[t] = dred[0];
        }
        __syncthreads();   // protect s_tile rewrite + smem reuse next tile
    }
}

// ---------------------------------------------------------------------------
__global__ void k_norm_factor()
{
    __shared__ double red[256];
    const int tid = threadIdx.x;
    double s = 0.0;
    for (int i = tid; i < NTILES; i += 256) s += g_partials[i];
    red[tid] = s;
    __syncthreads();
    #pragma unroll
    for (int off = 128; off > 0; off >>= 1) {
        if (tid < off) red[tid] += red[tid + off];
        __syncthreads();
    }
    if (tid == 0) {
        const double norm = sqrt(red[0]);
        g_factor = (norm > HOMEO_TARGET) ? (float)(HOMEO_TARGET / (norm + 1e-6)) : 1.0f;
    }
}

__global__ __launch_bounds__(256) void k_finalize(
    const float* __restrict__ slow, float* __restrict__ fout, float* __restrict__ sout)
{
    const float fac = g_factor;
    const size_t i = (size_t)blockIdx.x * blockDim.x + threadIdx.x;
    float4 f = ((const float4*)fout)[i];
    f.x *= fac; f.y *= fac; f.z *= fac; f.w *= fac;
    ((float4*)fout)[i] = f;
    const float4 sl = ((const float4*)slow)[i];
    float4 so;
    so.x = SLOW_DECAY * sl.x + SLOW_LR * f.x;
    so.y = SLOW_DECAY * sl.y + SLOW_LR * f.y;
    so.z = SLOW_DECAY * sl.z + SLOW_LR * f.z;
    so.w = SLOW_DECAY * sl.w + SLOW_LR * f.w;
    ((float4*)sout)[i] = so;
}

// ---------------------------------------------------------------------------
extern "C" void kernel_launch(void* const* d_in, const int* in_sizes, int n_in,
                              void* d_out, int out_size)
{
    const float* x    = (const float*)d_in[0];
    const float* w    = (const float*)d_in[1];
    const float* fast = (const float*)d_in[2];
    const float* slow = (const float*)d_in[3];

    float* out   = (float*)d_out;
    float* y_out = out;
    float* f_out = out + (size_t)TOK * DOUT;
    float* s_out = f_out + ELEMS;

    __nv_bfloat16 *whi, *wlo, *xhi, *xlo, *yrhi, *yrlo;
    cudaGetSymbolAddress((void**)&whi,  g_whi);
    cudaGetSymbolAddress((void**)&wlo,  g_wlo);
    cudaGetSymbolAddress((void**)&xhi,  g_xhi);
    cudaGetSymbolAddress((void**)&xlo,  g_xlo);
    cudaGetSymbolAddress((void**)&yrhi, g_yrhi);
    cudaGetSymbolAddress((void**)&yrlo, g_yrlo);

    cudaFuncSetAttribute(k_gemm_mma<0>, cudaFuncAttributeMaxDynamicSharedMemorySize, DYN_SMEM);
    cudaFuncSetAttribute(k_gemm_mma<1>, cudaFuncAttributeMaxDynamicSharedMemorySize, DYN_SMEM);

    // 1) fused prep: w_eff quantize+split AND X split (also resets tile counters)
    k_prep<<<4096 + 16384, 256>>>(w, fast, slow, x, whi, wlo, xhi, xlo);
    // 2) Y = X @ w_eff^T (persistent); epilogue emits relu(Y) bf16 hi/lo
    k_gemm_mma<0><<<NPERSIST, 256, DYN_SMEM>>>(xhi, xlo, whi, wlo, nullptr, y_out, yrhi, yrlo);
    // 3) new_fast (unscaled) = 0.95*fast + 0.05*(reluY^T @ X)/TOK (persistent), + partials
    k_gemm_mma<1><<<NPERSIST, 256, DYN_SMEM>>>(yrhi, yrlo, xhi, xlo, fast, f_out, nullptr, nullptr);
    // 4) norm -> factor
    k_norm_factor<<<1, 256>>>();
    // 5) scale fast, compute slow
    k_finalize<<<(unsigned)(ELEMS / 4 / 256), 256>>>(slow, f_out, s_out);
}

// round 12
// speedup vs baseline: 1.3628x; 1.2301x over previous
#include <cuda_runtime.h>
#include <cuda.h>
#include <cuda_bf16.h>
#include <stdint.h>
#include <math.h>

// ---------------------------------------------------------------------------
// Shapes (fixed)
#define TOK   4096
#define DIN   4096
#define DOUT  4096
#define ELEMS ((size_t)DOUT * (size_t)DIN)

#define FAST_DECAY 0.95f
#define FAST_LR    0.05f
#define SLOW_DECAY 0.99f
#define SLOW_LR    0.01f
#define HOMEO_TARGET 5.0

// CTA tile 128x128x32(bf16), 8 warps (4m x 2n), warp tile 32x64,
// TMA loads + 3-stage mbarrier pipeline, 2 CTAs/SM.
#define BK       32
#define NCHUNK   (4096 / BK)         // 128
#define NTILES   1024
#define TILE_B   8192                // one operand tile: 8KB (swizzled)
#define STAGE_B  (4 * TILE_B)        // 32KB
#define NSTAGE   3
#define DYN_SMEM (NSTAGE * STAGE_B + 1024)   // 99328; x2 CTAs = 194KB < 228KB

// ---------------------------------------------------------------------------
// Scratch
__device__ __nv_bfloat16 g_whi[ELEMS], g_wlo[ELEMS];     // w_eff split, K-major
__device__ __nv_bfloat16 g_xhi[ELEMS], g_xlo[ELEMS];     // X split [TOK, DIN]
__device__ __nv_bfloat16 g_yrhi[ELEMS], g_yrlo[ELEMS];   // relu(Y) split [TOK, DOUT]
__device__ double g_partials[NTILES];
__device__ float  g_factor;

// ---------------------------------------------------------------------------
__device__ __forceinline__ uint32_t smem_u32(const void* p) {
    uint32_t a;
    asm("{ .reg .u64 t; cvta.to.shared.u64 t, %1; cvt.u32.u64 %0, t; }" : "=r"(a) : "l"(p));
    return a;
}
__device__ __forceinline__ void mma_bf16(float* c, const uint32_t* a, const uint32_t* b) {
    asm volatile(
        "mma.sync.aligned.m16n8k16.row.col.f32.bf16.bf16.f32 "
        "{%0,%1,%2,%3}, {%4,%5,%6,%7}, {%8,%9}, {%0,%1,%2,%3};"
        : "+f"(c[0]), "+f"(c[1]), "+f"(c[2]), "+f"(c[3])
        : "r"(a[0]), "r"(a[1]), "r"(a[2]), "r"(a[3]), "r"(b[0]), "r"(b[1]));
}
#define LDSM4(R, A) \
    asm volatile("ldmatrix.sync.aligned.m8n8.x4.shared.b16 {%0,%1,%2,%3}, [%4];" \
        : "=r"((R)[0]), "=r"((R)[1]), "=r"((R)[2]), "=r"((R)[3]) : "r"(A))
#define LDSM4T(R, A) \
    asm volatile("ldmatrix.sync.aligned.m8n8.x4.trans.shared.b16 {%0,%1,%2,%3}, [%4];" \
        : "=r"((R)[0]), "=r"((R)[1]), "=r"((R)[2]), "=r"((R)[3]) : "r"(A))

#define MBARRIER_INIT(addr, cnt) \
    asm volatile("mbarrier.init.shared.b64 [%0], %1;" :: "r"(addr), "r"((uint32_t)(cnt)) : "memory")
#define MBARRIER_EXPECT_TX(addr, bytes) \
    asm volatile("mbarrier.arrive.expect_tx.shared.b64 _, [%0], %1;" \
                 :: "r"(addr), "r"((uint32_t)(bytes)) : "memory")
#define MBARRIER_WAIT_PARITY(addr, par) do {                                          \
    uint32_t _m = (addr); uint32_t _p = (uint32_t)(par); uint32_t _d;                 \
    asm volatile("{\n\t.reg .pred p;\n\t"                                             \
        "mbarrier.try_wait.parity.acquire.cta.shared::cta.b64 p, [%1], %2;\n\t"       \
        "selp.b32 %0, 1, 0, p;\n\t}" : "=r"(_d) : "r"(_m), "r"(_p) : "memory");       \
    if (!_d) {                                                                        \
        asm volatile("{\n\t.reg .pred P1;\n\t"                                        \
            "W_%=:\n\t"                                                               \
            "mbarrier.try_wait.parity.acquire.cta.shared::cta.b64 P1, [%0], %1, 0x989680;\n\t" \
            "@P1 bra.uni D_%=;\n\t"                                                   \
            "bra.uni W_%=;\n\t"                                                       \
            "D_%=:\n\t}" :: "r"(_m), "r"(_p) : "memory");                             \
    }                                                                                 \
} while (0)

__device__ __forceinline__ void tma2d(uint32_t dst, const CUtensorMap* m,
                                      int cx, int cy, uint32_t mbar) {
    asm volatile(
        "cp.async.bulk.tensor.2d.shared::cta.global.tile.mbarrier::complete_tx::bytes "
        "[%0], [%1, {%2, %3}], [%4];"
        :: "r"(dst), "l"(m), "r"(cx), "r"(cy), "r"(mbar) : "memory");
}

// ---------------------------------------------------------------------------
// Fused prep: blocks [0,4096): per-row quantize+combine w_eff -> whi/wlo
//             blocks [4096,20480): elementwise split X -> xhi/xlo
__global__ __launch_bounds__(256) void k_prep(
    const float* __restrict__ w, const float* __restrict__ fast, const float* __restrict__ slow,
    const float* __restrict__ x,
    __nv_bfloat16* __restrict__ whi, __nv_bfloat16* __restrict__ wlo,
    __nv_bfloat16* __restrict__ xhi, __nv_bfloat16* __restrict__ xlo)
{
    const int tid = threadIdx.x;
    if (blockIdx.x >= 4096) {
        const size_t i = ((size_t)(blockIdx.x - 4096) * 256 + tid) * 4;
        float4 v = *(const float4*)(x + i);
        union { __nv_bfloat16 b[4]; uint64_t u; } H, L;
        float f[4] = {v.x, v.y, v.z, v.w};
        #pragma unroll
        for (int j = 0; j < 4; j++) {
            __nv_bfloat16 h = __float2bfloat16_rn(f[j]);
            H.b[j] = h;
            L.b[j] = __float2bfloat16_rn(f[j] - __bfloat162float(h));
        }
        *(uint64_t*)(xhi + i) = H.u;
        *(uint64_t*)(xlo + i) = L.u;
        return;
    }
    const int row = blockIdx.x;
    const size_t base = (size_t)row * DIN;

    float s = 0.f;
    for (int i = tid; i < DIN; i += 256) s += fabsf(w[base + i]);
    __shared__ float red[256];
    red[tid] = s;
    __syncthreads();
    #pragma unroll
    for (int off = 128; off > 0; off >>= 1) {
        if (tid < off) red[tid] += red[tid + off];
        __syncthreads();
    }
    float scale = fmaxf(red[0] * (1.0f / (float)DIN), 1e-5f);
    const float inv_scale = 1.0f / scale;

    for (int i = tid; i < DIN; i += 256) {
        const size_t idx = base + i;
        float q = rintf(w[idx] * inv_scale);
        q = fminf(fmaxf(q, -1.0f), 1.0f);
        float v = q * scale + 0.1f * fast[idx] + 0.05f * slow[idx];
        __nv_bfloat16 h = __float2bfloat16_rn(v);
        whi[idx] = h;
        wlo[idx] = __float2bfloat16_rn(v - __bfloat162float(h));
    }
}

// ---------------------------------------------------------------------------
// bf16x3 GEMM with TMA operand loads + 3-stage mbarrier pipeline.
// MODE 0 (NT): tiles 128 rows x 64B, SW64. D = A@B^T; epilogue y + relu split.
// MODE 1 (TT): tiles [2 halves][32 x 128B], SW128, ldmatrix.trans.
//              Epilogue fast-trace EMA + sumsq partials.
// ---------------------------------------------------------------------------
template<int MODE>
__global__ __launch_bounds__(256, 2) void k_gemm_tma(
    const __grid_constant__ CUtensorMap mAhi, const __grid_constant__ CUtensorMap mAlo,
    const __grid_constant__ CUtensorMap mBhi, const __grid_constant__ CUtensorMap mBlo,
    const float* __restrict__ fast, float* __restrict__ out,
    __nv_bfloat16* __restrict__ ohi, __nv_bfloat16* __restrict__ olo)
{
    constexpr bool TRANS = (MODE == 1);

    extern __shared__ uint32_t dsm[];
    __shared__ double dred[256];
    __shared__ __align__(8) uint64_t mbars[NSTAGE];

    const int tid  = threadIdx.x;
    const int lane = tid & 31;
    const int wid  = tid >> 5;
    const int g    = lane >> 2;
    const int tig  = lane & 3;

    // supertile swizzle: 4 groups x (32 m-tiles x 8 n-tiles)
    const int bid   = blockIdx.x;
    const int group = bid >> 8;
    const int rem   = bid & 255;
    const int am  = (rem >> 3) * 128;
    const int bn  = (group * 8 + (rem & 7)) * 128;

    const int wm = (wid & 3) * 32;
    const int wn = (wid >> 2) * 64;

    // 1024-aligned smem base
    const uint32_t sraw = smem_u32(dsm);
    const uint32_t sbase = (sraw + 1023u) & ~1023u;

    uint32_t mb[NSTAGE];
    #pragma unroll
    for (int s = 0; s < NSTAGE; s++) mb[s] = smem_u32(&mbars[s]);

    if (tid == 0) {
        #pragma unroll
        for (int s = 0; s < NSTAGE; s++) MBARRIER_INIT(mb[s], 1);
    }
    __syncthreads();

    const CUtensorMap* maps[4] = {&mAhi, &mAlo, &mBhi, &mBlo};
    const int cbase[4] = {am, am, bn, bn};

    // ---- per-lane ldmatrix offsets (within a tile, swizzled) ----
    uint32_t aoff[2], boff[4];   // byte offsets excluding stage/op base
    uint32_t asw[2], bsw[4];     // NT swizzle sel (unused in TRANS)
    const int ld_row = ((lane >> 3) & 1) * 8 + (lane & 7);
    const int lh = lane >> 4;            // 16B-unit select (NT)
    if (!TRANS) {
        #pragma unroll
        for (int mt = 0; mt < 2; mt++) {
            const int r = wm + mt * 16 + ld_row;
            aoff[mt] = (uint32_t)(r * 64);
            asw[mt]  = (uint32_t)((r >> 1) & 3);
        }
        #pragma unroll
        for (int p = 0; p < 4; p++) {
            const int r = wn + p * 16 + ld_row;
            boff[p] = (uint32_t)(r * 64);
            bsw[p]  = (uint32_t)((r >> 1) & 3);
        }
    } else {
        const int kr = (lane >> 4) * 8 + (lane & 7);
        const int cb16 = ((lane >> 3) & 1) * 16;
        #pragma unroll
        for (int mt = 0; mt < 2; mt++) {
            const int colb = wm * 2 + mt * 32 + cb16;
            aoff[mt] = (uint32_t)((colb >> 7) * 4096 + kr * 128 +
                                  ((((colb & 127) >> 4) ^ (kr & 7)) << 4));
        }
        #pragma unroll
        for (int p = 0; p < 4; p++) {
            const int colb = wn * 2 + p * 32 + cb16;
            boff[p] = (uint32_t)((colb >> 7) * 4096 + kr * 128 +
                                 ((((colb & 127) >> 4) ^ (kr & 7)) << 4));
        }
    }

    float acc[2][8][4];
    #pragma unroll
    for (int mt = 0; mt < 2; mt++)
        #pragma unroll
        for (int nt = 0; nt < 8; nt++)
            #pragma unroll
            for (int r = 0; r < 4; r++) acc[mt][nt][r] = 0.f;

    // ---- TMA issue helper ----
    auto issue = [&](int stage, int chunk) {
        const uint32_t sdst = sbase + (uint32_t)stage * STAGE_B;
        MBARRIER_EXPECT_TX(mb[stage], STAGE_B);
        const int k0 = chunk * BK;
        #pragma unroll
        for (int op = 0; op < 4; op++) {
            if (!TRANS) {
                tma2d(sdst + op * TILE_B, maps[op], k0, cbase[op], mb[stage]);
            } else {
                tma2d(sdst + op * TILE_B,        maps[op], cbase[op],      k0, mb[stage]);
                tma2d(sdst + op * TILE_B + 4096, maps[op], cbase[op] + 64, k0, mb[stage]);
            }
        }
    };

    if (tid == 0) { issue(0, 0); issue(1, 1); }

    int sc = 0;
    uint32_t phb = 0;
    for (int c = 0; c < NCHUNK; c++) {
        MBARRIER_WAIT_PARITY(mb[sc], (phb >> sc) & 1u);
        phb ^= (1u << sc);
        __syncthreads();   // all warps done with chunk c-1 (its stage may be refilled)
        if (c + 2 < NCHUNK) {
            int sn = sc + 2; if (sn >= NSTAGE) sn -= NSTAGE;
            if (tid == 0) issue(sn, c + 2);
        }

        const uint32_t stg = sbase + (uint32_t)sc * STAGE_B;
        #pragma unroll
        for (int ks = 0; ks < 2; ks++) {
            uint32_t a[2][2][4];
            #pragma unroll
            for (int mt = 0; mt < 2; mt++)
                #pragma unroll
                for (int t = 0; t < 2; t++) {
                    uint32_t addr;
                    if (!TRANS)
                        addr = stg + t * TILE_B + aoff[mt] +
                               ((((uint32_t)(ks * 2 + lh)) ^ asw[mt]) << 4);
                    else
                        addr = stg + t * TILE_B + aoff[mt] + ks * 2048;
                    if (!TRANS) { LDSM4(a[mt][t], addr); } else { LDSM4T(a[mt][t], addr); }
                }
            #pragma unroll
            for (int pp = 0; pp < 2; pp++) {
                uint32_t bh[2][4], bl[2][4];
                #pragma unroll
                for (int q = 0; q < 2; q++) {
                    const int p = pp * 2 + q;
                    uint32_t ah, al;
                    if (!TRANS) {
                        const uint32_t u = (((uint32_t)(ks * 2 + lh)) ^ bsw[p]) << 4;
                        ah = stg + 2 * TILE_B + boff[p] + u;
                        al = stg + 3 * TILE_B + boff[p] + u;
                        LDSM4(bh[q], ah); LDSM4(bl[q], al);
                    } else {
                        ah = stg + 2 * TILE_B + boff[p] + ks * 2048;
                        al = stg + 3 * TILE_B + boff[p] + ks * 2048;
                        LDSM4T(bh[q], ah); LDSM4T(bl[q], al);
                    }
                }
                #pragma unroll
                for (int q = 0; q < 2; q++) {
                    const int p = pp * 2 + q;
                    uint32_t b0[2] = {bh[q][0], bh[q][2]}, b1[2] = {bh[q][1], bh[q][3]};
                    mma_bf16(acc[0][2*p],   a[0][0], b0);
                    mma_bf16(acc[0][2*p+1], a[0][0], b1);
                    mma_bf16(acc[1][2*p],   a[1][0], b0);
                    mma_bf16(acc[1][2*p+1], a[1][0], b1);
                }
                #pragma unroll
                for (int q = 0; q < 2; q++) {
                    const int p = pp * 2 + q;
                    uint32_t b0[2] = {bl[q][0], bl[q][2]}, b1[2] = {bl[q][1], bl[q][3]};
                    mma_bf16(acc[0][2*p],   a[0][0], b0);
                    mma_bf16(acc[0][2*p+1], a[0][0], b1);
                    mma_bf16(acc[1][2*p],   a[1][0], b0);
                    mma_bf16(acc[1][2*p+1], a[1][0], b1);
                }
                #pragma unroll
                for (int q = 0; q < 2; q++) {
                    const int p = pp * 2 + q;
                    uint32_t b0[2] = {bh[q][0], bh[q][2]}, b1[2] = {bh[q][1], bh[q][3]};
                    mma_bf16(acc[0][2*p],   a[0][1], b0);
                    mma_bf16(acc[0][2*p+1], a[0][1], b1);
                    mma_bf16(acc[1][2*p],   a[1][1], b0);
                    mma_bf16(acc[1][2*p+1], a[1][1], b1);
                }
            }
        }
        sc = (sc == NSTAGE - 1) ? 0 : sc + 1;
    }

    // ---- epilogue ----
    double ss = 0.0;
    const float inv_tok = 1.0f / (float)TOK;
    #pragma unroll
    for (int mt = 0; mt < 2; mt++) {
        const int r0 = am + wm + mt * 16 + g;
        #pragma unroll
        for (int nt = 0; nt < 8; nt++) {
            const int col = bn + wn + nt * 8 + tig * 2;
            #pragma unroll
            for (int half = 0; half < 2; half++) {
                const int r = r0 + half * 8;
                const float d0 = acc[mt][nt][half * 2 + 0];
                const float d1 = acc[mt][nt][half * 2 + 1];
                const size_t o = (size_t)r * 4096 + col;
                if (MODE == 0) {
                    *(float2*)(out + o) = make_float2(d0, d1);
                    const float r0f = fmaxf(d0, 0.f), r1f = fmaxf(d1, 0.f);
                    union { __nv_bfloat16 b[2]; uint32_t u; } H, L;
                    H.b[0] = __float2bfloat16_rn(r0f);
                    H.b[1] = __float2bfloat16_rn(r1f);
                    L.b[0] = __float2bfloat16_rn(r0f - __bfloat162float(H.b[0]));
                    L.b[1] = __float2bfloat16_rn(r1f - __bfloat162float(H.b[1]));
                    *(uint32_t*)(ohi + o) = H.u;
                    *(uint32_t*)(olo + o) = L.u;
                } else {
                    const float2 fa = *(const float2*)(fast + o);
                    float2 v;
                    v.x = FAST_DECAY * fa.x + FAST_LR * (d0 * inv_tok);
                    v.y = FAST_DECAY * fa.y + FAST_LR * (d1 * inv_tok);
                    *(float2*)(out + o) = v;
                    ss += (double)v.x * v.x + (double)v.y * v.y;
                }
            }
        }
    }
    if (MODE == 1) {
        dred[tid] = ss;
        __syncthreads();
        #pragma unroll
        for (int off = 128; off > 0; off >>= 1) {
            if (tid < off) dred[tid] += dred[tid + off];
            __syncthreads();
        }
        if (tid == 0) g_partials[blockIdx.x] = dred[0];
    }
}

// ---------------------------------------------------------------------------
__global__ void k_norm_factor()
{
    __shared__ double red[256];
    const int tid = threadIdx.x;
    double s = 0.0;
    for (int i = tid; i < NTILES; i += 256) s += g_partials[i];
    red[tid] = s;
    __syncthreads();
    #pragma unroll
    for (int off = 128; off > 0; off >>= 1) {
        if (tid < off) red[tid] += red[tid + off];
        __syncthreads();
    }
    if (tid == 0) {
        const double norm = sqrt(red[0]);
        g_factor = (norm > HOMEO_TARGET) ? (float)(HOMEO_TARGET / (norm + 1e-6)) : 1.0f;
    }
}

__global__ __launch_bounds__(256) void k_finalize(
    const float* __restrict__ slow, float* __restrict__ fout, float* __restrict__ sout)
{
    const float fac = g_factor;
    const size_t i = (size_t)blockIdx.x * blockDim.x + threadIdx.x;
    float4 f = ((const float4*)fout)[i];
    f.x *= fac; f.y *= fac; f.z *= fac; f.w *= fac;
    ((float4*)fout)[i] = f;
    const float4 sl = ((const float4*)slow)[i];
    float4 so;
    so.x = SLOW_DECAY * sl.x + SLOW_LR * f.x;
    so.y = SLOW_DECAY * sl.y + SLOW_LR * f.y;
    so.z = SLOW_DECAY * sl.z + SLOW_LR * f.z;
    so.w = SLOW_DECAY * sl.w + SLOW_LR * f.w;
    ((float4*)sout)[i] = so;
}

// ---------------------------------------------------------------------------
typedef CUresult (*PFN_tmEncode)(
    CUtensorMap*, CUtensorMapDataType, cuuint32_t, void*,
    const cuuint64_t*, const cuuint64_t*, const cuuint32_t*, const cuuint32_t*,
    CUtensorMapInterleave, CUtensorMapSwizzle, CUtensorMapL2promotion,
    CUtensorMapFloatOOBfill);

static void make_map(PFN_tmEncode enc, CUtensorMap* m, void* ptr,
                     int box_inner, int box_outer, CUtensorMapSwizzle swz)
{
    cuuint64_t dims[2]    = {4096, 4096};
    cuuint64_t strides[1] = {4096 * 2};
    cuuint32_t box[2]     = {(cuuint32_t)box_inner, (cuuint32_t)box_outer};
    cuuint32_t est[2]     = {1, 1};
    enc(m, CU_TENSOR_MAP_DATA_TYPE_BFLOAT16, 2, ptr, dims, strides, box, est,
        CU_TENSOR_MAP_INTERLEAVE_NONE, swz,
        CU_TENSOR_MAP_L2_PROMOTION_L2_128B, CU_TENSOR_MAP_FLOAT_OOB_FILL_NONE);
}

extern "C" void kernel_launch(void* const* d_in, const int* in_sizes, int n_in,
                              void* d_out, int out_size)
{
    const float* x    = (const float*)d_in[0];
    const float* w    = (const float*)d_in[1];
    const float* fast = (const float*)d_in[2];
    const float* slow = (const float*)d_in[3];

    float* out   = (float*)d_out;
    float* y_out = out;
    float* f_out = out + (size_t)TOK * DOUT;
    float* s_out = f_out + ELEMS;

    __nv_bfloat16 *whi, *wlo, *xhi, *xlo, *yrhi, *yrlo;
    cudaGetSymbolAddress((void**)&whi,  g_whi);
    cudaGetSymbolAddress((void**)&wlo,  g_wlo);
    cudaGetSymbolAddress((void**)&xhi,  g_xhi);
    cudaGetSymbolAddress((void**)&xlo,  g_xlo);
    cudaGetSymbolAddress((void**)&yrhi, g_yrhi);
    cudaGetSymbolAddress((void**)&yrlo, g_yrlo);

    // Driver entry point for tensor-map encoding (no -lcuda needed).
    void* sym = nullptr;
    cudaDriverEntryPointQueryResult qr;
    cudaGetDriverEntryPoint("cuTensorMapEncodeTiled", &sym, cudaEnableDefault, &qr);
    PFN_tmEncode enc = (PFN_tmEncode)sym;

    // NT maps (GEMM1): box {32 k-elems, 128 rows}, SW64
    CUtensorMap mXhi, mXlo, mWhi, mWlo;
    make_map(enc, &mXhi, xhi, 32, 128, CU_TENSOR_MAP_SWIZZLE_64B);
    make_map(enc, &mXlo, xlo, 32, 128, CU_TENSOR_MAP_SWIZZLE_64B);
    make_map(enc, &mWhi, whi, 32, 128, CU_TENSOR_MAP_SWIZZLE_64B);
    make_map(enc, &mWlo, wlo, 32, 128, CU_TENSOR_MAP_SWIZZLE_64B);
    // TT maps (GEMM2): box {64 cols, 32 k-rows}, SW128
    CUtensorMap mYhi, mYlo, mXThi, mXTlo;
    make_map(enc, &mYhi,  yrhi, 64, 32, CU_TENSOR_MAP_SWIZZLE_128B);
    make_map(enc, &mYlo,  yrlo, 64, 32, CU_TENSOR_MAP_SWIZZLE_128B);
    make_map(enc, &mXThi, xhi,  64, 32, CU_TENSOR_MAP_SWIZZLE_128B);
    make_map(enc, &mXTlo, xlo,  64, 32, CU_TENSOR_MAP_SWIZZLE_128B);

    cudaFuncSetAttribute(k_gemm_tma<0>, cudaFuncAttributeMaxDynamicSharedMemorySize, DYN_SMEM);
    cudaFuncSetAttribute(k_gemm_tma<1>, cudaFuncAttributeMaxDynamicSharedMemorySize, DYN_SMEM);

    // 1) fused prep: w_eff quantize+split AND X split
    k_prep<<<4096 + 16384, 256>>>(w, fast, slow, x, whi, wlo, xhi, xlo);
    // 2) Y = X @ w_eff^T (TMA); epilogue emits relu(Y) bf16 hi/lo
    k_gemm_tma<0><<<NTILES, 256, DYN_SMEM>>>(mXhi, mXlo, mWhi, mWlo,
                                             nullptr, y_out, yrhi, yrlo);
    // 3) new_fast (unscaled) = 0.95*fast + 0.05*(reluY^T @ X)/TOK (TMA), + partials
    k_gemm_tma<1><<<NTILES, 256, DYN_SMEM>>>(mYhi, mYlo, mXThi, mXTlo,
                                             fast, f_out, nullptr, nullptr);
    // 4) norm -> factor
    k_norm_factor<<<1, 256>>>();
    // 5) scale fast, compute slow
    k_finalize<<<(unsigned)(ELEMS / 4 / 256), 256>>>(slow, f_out, s_out);
}

// round 13
// speedup vs baseline: 1.3640x; 1.0009x over previous
#include <cuda_runtime.h>
#include <cuda.h>
#include <cuda_bf16.h>
#include <stdint.h>
#include <math.h>

// ---------------------------------------------------------------------------
// Shapes (fixed)
#define TOK   4096
#define DIN   4096
#define DOUT  4096
#define ELEMS ((size_t)DOUT * (size_t)DIN)

#define FAST_DECAY 0.95f
#define FAST_LR    0.05f
#define SLOW_DECAY 0.99f
#define SLOW_LR    0.01f
#define HOMEO_TARGET 5.0

// CTA tile 128x128x32(bf16), 8 warps (4m x 2n), warp tile 32x64,
// TMA loads + 3-stage mbarrier pipeline, 2 CTAs/SM.
#define BK       32
#define NCHUNK   (4096 / BK)         // 128
#define NTILES   1024
#define TILE_B   8192                // one operand tile: 8KB (swizzled)
#define STAGE_B  (4 * TILE_B)        // 32KB
#define NSTAGE   3
#define DYN_SMEM (NSTAGE * STAGE_B + 1024)   // 99328; x2 CTAs = 194KB < 228KB

// ---------------------------------------------------------------------------
// Scratch
__device__ __nv_bfloat16 g_whi[ELEMS], g_wlo[ELEMS];     // w_eff split, K-major
__device__ __nv_bfloat16 g_xhi[ELEMS], g_xlo[ELEMS];     // X split [TOK, DIN]
__device__ __nv_bfloat16 g_yrhi[ELEMS], g_yrlo[ELEMS];   // relu(Y) split [TOK, DOUT]
__device__ double g_partials[NTILES];
__device__ float  g_factor;

// ---------------------------------------------------------------------------
__device__ __forceinline__ uint32_t smem_u32(const void* p) {
    uint32_t a;
    asm("{ .reg .u64 t; cvta.to.shared.u64 t, %1; cvt.u32.u64 %0, t; }" : "=r"(a) : "l"(p));
    return a;
}
__device__ __forceinline__ void mma_bf16(float* c, const uint32_t* a, const uint32_t* b) {
    asm volatile(
        "mma.sync.aligned.m16n8k16.row.col.f32.bf16.bf16.f32 "
        "{%0,%1,%2,%3}, {%4,%5,%6,%7}, {%8,%9}, {%0,%1,%2,%3};"
        : "+f"(c[0]), "+f"(c[1]), "+f"(c[2]), "+f"(c[3])
        : "r"(a[0]), "r"(a[1]), "r"(a[2]), "r"(a[3]), "r"(b[0]), "r"(b[1]));
}
#define LDSM4(R, A) \
    asm volatile("ldmatrix.sync.aligned.m8n8.x4.shared.b16 {%0,%1,%2,%3}, [%4];" \
        : "=r"((R)[0]), "=r"((R)[1]), "=r"((R)[2]), "=r"((R)[3]) : "r"(A))
#define LDSM4T(R, A) \
    asm volatile("ldmatrix.sync.aligned.m8n8.x4.trans.shared.b16 {%0,%1,%2,%3}, [%4];" \
        : "=r"((R)[0]), "=r"((R)[1]), "=r"((R)[2]), "=r"((R)[3]) : "r"(A))

#define MBARRIER_INIT(addr, cnt) \
    asm volatile("mbarrier.init.shared.b64 [%0], %1;" :: "r"(addr), "r"((uint32_t)(cnt)) : "memory")
#define MBARRIER_EXPECT_TX(addr, bytes) \
    asm volatile("mbarrier.arrive.expect_tx.shared.b64 _, [%0], %1;" \
                 :: "r"(addr), "r"((uint32_t)(bytes)) : "memory")
#define MBARRIER_WAIT_PARITY(addr, par) do {                                          \
    uint32_t _m = (addr); uint32_t _p = (uint32_t)(par); uint32_t _d;                 \
    asm volatile("{\n\t.reg .pred p;\n\t"                                             \
        "mbarrier.try_wait.parity.acquire.cta.shared::cta.b64 p, [%1], %2;\n\t"       \
        "selp.b32 %0, 1, 0, p;\n\t}" : "=r"(_d) : "r"(_m), "r"(_p) : "memory");       \
    if (!_d) {                                                                        \
        asm volatile("{\n\t.reg .pred P1;\n\t"                                        \
            "W_%=:\n\t"                                                               \
            "mbarrier.try_wait.parity.acquire.cta.shared::cta.b64 P1, [%0], %1, 0x989680;\n\t" \
            "@P1 bra.uni D_%=;\n\t"                                                   \
            "bra.uni W_%=;\n\t"                                                       \
            "D_%=:\n\t}" :: "r"(_m), "r"(_p) : "memory");                             \
    }                                                                                 \
} while (0)

__device__ __forceinline__ void tma2d(uint32_t dst, const CUtensorMap* m,
                                      int cx, int cy, uint32_t mbar) {
    asm volatile(
        "cp.async.bulk.tensor.2d.shared::cta.global.tile.mbarrier::complete_tx::bytes "
        "[%0], [%1, {%2, %3}], [%4];"
        :: "r"(dst), "l"(m), "r"(cx), "r"(cy), "r"(mbar) : "memory");
}

// ---------------------------------------------------------------------------
// Fused prep: blocks [0,4096): per-row quantize+combine w_eff -> whi/wlo
//             blocks [4096,20480): elementwise split X -> xhi/xlo
__global__ __launch_bounds__(256) void k_prep(
    const float* __restrict__ w, const float* __restrict__ fast, const float* __restrict__ slow,
    const float* __restrict__ x,
    __nv_bfloat16* __restrict__ whi, __nv_bfloat16* __restrict__ wlo,
    __nv_bfloat16* __restrict__ xhi, __nv_bfloat16* __restrict__ xlo)
{
    const int tid = threadIdx.x;
    if (blockIdx.x >= 4096) {
        const size_t i = ((size_t)(blockIdx.x - 4096) * 256 + tid) * 4;
        float4 v = *(const float4*)(x + i);
        union { __nv_bfloat16 b[4]; uint64_t u; } H, L;
        float f[4] = {v.x, v.y, v.z, v.w};
        #pragma unroll
        for (int j = 0; j < 4; j++) {
            __nv_bfloat16 h = __float2bfloat16_rn(f[j]);
            H.b[j] = h;
            L.b[j] = __float2bfloat16_rn(f[j] - __bfloat162float(h));
        }
        *(uint64_t*)(xhi + i) = H.u;
        *(uint64_t*)(xlo + i) = L.u;
        return;
    }
    const int row = blockIdx.x;
    const size_t base = (size_t)row * DIN;

    float s = 0.f;
    for (int i = tid; i < DIN; i += 256) s += fabsf(w[base + i]);
    __shared__ float red[256];
    red[tid] = s;
    __syncthreads();
    #pragma unroll
    for (int off = 128; off > 0; off >>= 1) {
        if (tid < off) red[tid] += red[tid + off];
        __syncthreads();
    }
    float scale = fmaxf(red[0] * (1.0f / (float)DIN), 1e-5f);
    const float inv_scale = 1.0f / scale;

    for (int i = tid; i < DIN; i += 256) {
        const size_t idx = base + i;
        float q = rintf(w[idx] * inv_scale);
        q = fminf(fmaxf(q, -1.0f), 1.0f);
        float v = q * scale + 0.1f * fast[idx] + 0.05f * slow[idx];
        __nv_bfloat16 h = __float2bfloat16_rn(v);
        whi[idx] = h;
        wlo[idx] = __float2bfloat16_rn(v - __bfloat162float(h));
    }
}

// ---------------------------------------------------------------------------
// bf16x3 GEMM with TMA operand loads + 3-stage mbarrier pipeline.
// MODE 0 (NT): tiles 128 rows x 64B, SW64. D = A@B^T; epilogue y + relu split.
// MODE 1 (TT): tiles [2 halves][32 x 128B], SW128, ldmatrix.trans.
//              Epilogue fast-trace EMA + sumsq partials.
// ---------------------------------------------------------------------------
template<int MODE>
__global__ __launch_bounds__(256, 2) void k_gemm_tma(
    const __grid_constant__ CUtensorMap mAhi, const __grid_constant__ CUtensorMap mAlo,
    const __grid_constant__ CUtensorMap mBhi, const __grid_constant__ CUtensorMap mBlo,
    const float* __restrict__ fast, float* __restrict__ out,
    __nv_bfloat16* __restrict__ ohi, __nv_bfloat16* __restrict__ olo)
{
    constexpr bool TRANS = (MODE == 1);

    extern __shared__ uint32_t dsm[];
    __shared__ double dred[256];
    __shared__ __align__(8) uint64_t mbars[NSTAGE];

    const int tid  = threadIdx.x;
    const int lane = tid & 31;
    const int wid  = tid >> 5;
    const int g    = lane >> 2;
    const int tig  = lane & 3;

    // supertile swizzle: 4 groups x (32 m-tiles x 8 n-tiles)
    const int bid   = blockIdx.x;
    const int group = bid >> 8;
    const int rem   = bid & 255;
    const int am  = (rem >> 3) * 128;
    const int bn  = (group * 8 + (rem & 7)) * 128;

    const int wm = (wid & 3) * 32;
    const int wn = (wid >> 2) * 64;

    // 1024-aligned smem base
    const uint32_t sraw = smem_u32(dsm);
    const uint32_t sbase = (sraw + 1023u) & ~1023u;

    uint32_t mb[NSTAGE];
    #pragma unroll
    for (int s = 0; s < NSTAGE; s++) mb[s] = smem_u32(&mbars[s]);

    if (tid == 0) {
        #pragma unroll
        for (int s = 0; s < NSTAGE; s++) MBARRIER_INIT(mb[s], 1);
    }
    __syncthreads();

    const CUtensorMap* maps[4] = {&mAhi, &mAlo, &mBhi, &mBlo};
    const int cbase[4] = {am, am, bn, bn};

    // ---- per-lane ldmatrix offsets (within a tile, swizzled) ----
    uint32_t aoff[2], boff[4];   // byte offsets excluding stage/op base
    uint32_t asw[2], bsw[4];     // NT swizzle sel (unused in TRANS)
    const int ld_row = ((lane >> 3) & 1) * 8 + (lane & 7);
    const int lh = lane >> 4;            // 16B-unit select (NT)
    if (!TRANS) {
        #pragma unroll
        for (int mt = 0; mt < 2; mt++) {
            const int r = wm + mt * 16 + ld_row;
            aoff[mt] = (uint32_t)(r * 64);
            asw[mt]  = (uint32_t)((r >> 1) & 3);
        }
        #pragma unroll
        for (int p = 0; p < 4; p++) {
            const int r = wn + p * 16 + ld_row;
            boff[p] = (uint32_t)(r * 64);
            bsw[p]  = (uint32_t)((r >> 1) & 3);
        }
    } else {
        const int kr = (lane >> 4) * 8 + (lane & 7);
        const int cb16 = ((lane >> 3) & 1) * 16;
        #pragma unroll
        for (int mt = 0; mt < 2; mt++) {
            const int colb = wm * 2 + mt * 32 + cb16;
            aoff[mt] = (uint32_t)((colb >> 7) * 4096 + kr * 128 +
                                  ((((colb & 127) >> 4) ^ (kr & 7)) << 4));
        }
        #pragma unroll
        for (int p = 0; p < 4; p++) {
            const int colb = wn * 2 + p * 32 + cb16;
            boff[p] = (uint32_t)((colb >> 7) * 4096 + kr * 128 +
                                 ((((colb & 127) >> 4) ^ (kr & 7)) << 4));
        }
    }

    float acc[2][8][4];
    #pragma unroll
    for (int mt = 0; mt < 2; mt++)
        #pragma unroll
        for (int nt = 0; nt < 8; nt++)
            #pragma unroll
            for (int r = 0; r < 4; r++) acc[mt][nt][r] = 0.f;

    // ---- TMA issue helper ----
    auto issue = [&](int stage, int chunk) {
        const uint32_t sdst = sbase + (uint32_t)stage * STAGE_B;
        MBARRIER_EXPECT_TX(mb[stage], STAGE_B);
        const int k0 = chunk * BK;
        #pragma unroll
        for (int op = 0; op < 4; op++) {
            if (!TRANS) {
                tma2d(sdst + op * TILE_B, maps[op], k0, cbase[op], mb[stage]);
            } else {
                tma2d(sdst + op * TILE_B,        maps[op], cbase[op],      k0, mb[stage]);
                tma2d(sdst + op * TILE_B + 4096, maps[op], cbase[op] + 64, k0, mb[stage]);
            }
        }
    };

    if (tid == 0) { issue(0, 0); issue(1, 1); }

    int sc = 0;
    uint32_t phb = 0;
    for (int c = 0; c < NCHUNK; c++) {
        MBARRIER_WAIT_PARITY(mb[sc], (phb >> sc) & 1u);
        phb ^= (1u << sc);
        __syncthreads();   // all warps done with chunk c-1 (its stage may be refilled)
        if (c + 2 < NCHUNK) {
            int sn = sc + 2; if (sn >= NSTAGE) sn -= NSTAGE;
            if (tid == 0) issue(sn, c + 2);
        }

        const uint32_t stg = sbase + (uint32_t)sc * STAGE_B;
        #pragma unroll
        for (int ks = 0; ks < 2; ks++) {
            uint32_t a[2][2][4];
            #pragma unroll
            for (int mt = 0; mt < 2; mt++)
                #pragma unroll
                for (int t = 0; t < 2; t++) {
                    uint32_t addr;
                    if (!TRANS)
                        addr = stg + t * TILE_B + aoff[mt] +
                               ((((uint32_t)(ks * 2 + lh)) ^ asw[mt]) << 4);
                    else
                        addr = stg + t * TILE_B + aoff[mt] + ks * 2048;
                    if (!TRANS) { LDSM4(a[mt][t], addr); } else { LDSM4T(a[mt][t], addr); }
                }
            #pragma unroll
            for (int pp = 0; pp < 2; pp++) {
                uint32_t bh[2][4], bl[2][4];
                #pragma unroll
                for (int q = 0; q < 2; q++) {
                    const int p = pp * 2 + q;
                    uint32_t ah, al;
                    if (!TRANS) {
                        const uint32_t u = (((uint32_t)(ks * 2 + lh)) ^ bsw[p]) << 4;
                        ah = stg + 2 * TILE_B + boff[p] + u;
                        al = stg + 3 * TILE_B + boff[p] + u;
                        LDSM4(bh[q], ah); LDSM4(bl[q], al);
                    } else {
                        ah = stg + 2 * TILE_B + boff[p] + ks * 2048;
                        al = stg + 3 * TILE_B + boff[p] + ks * 2048;
                        LDSM4T(bh[q], ah); LDSM4T(bl[q], al);
                    }
                }
                #pragma unroll
                for (int q = 0; q < 2; q++) {
                    const int p = pp * 2 + q;
                    uint32_t b0[2] = {bh[q][0], bh[q][2]}, b1[2] = {bh[q][1], bh[q][3]};
                    mma_bf16(acc[0][2*p],   a[0][0], b0);
                    mma_bf16(acc[0][2*p+1], a[0][0], b1);
                    mma_bf16(acc[1][2*p],   a[1][0], b0);
                    mma_bf16(acc[1][2*p+1], a[1][0], b1);
                }
                #pragma unroll
                for (int q = 0; q < 2; q++) {
                    const int p = pp * 2 + q;
                    uint32_t b0[2] = {bl[q][0], bl[q][2]}, b1[2] = {bl[q][1], bl[q][3]};
                    mma_bf16(acc[0][2*p],   a[0][0], b0);
                    mma_bf16(acc[0][2*p+1], a[0][0], b1);
                    mma_bf16(acc[1][2*p],   a[1][0], b0);
                    mma_bf16(acc[1][2*p+1], a[1][0], b1);
                }
                #pragma unroll
                for (int q = 0; q < 2; q++) {
                    const int p = pp * 2 + q;
                    uint32_t b0[2] = {bh[q][0], bh[q][2]}, b1[2] = {bh[q][1], bh[q][3]};
                    mma_bf16(acc[0][2*p],   a[0][1], b0);
                    mma_bf16(acc[0][2*p+1], a[0][1], b1);
                    mma_bf16(acc[1][2*p],   a[1][1], b0);
                    mma_bf16(acc[1][2*p+1], a[1][1], b1);
                }
            }
        }
        sc = (sc == NSTAGE - 1) ? 0 : sc + 1;
    }

    // ---- epilogue ----
    double ss = 0.0;
    const float inv_tok = 1.0f / (float)TOK;
    #pragma unroll
    for (int mt = 0; mt < 2; mt++) {
        const int r0 = am + wm + mt * 16 + g;
        #pragma unroll
        for (int nt = 0; nt < 8; nt++) {
            const int col = bn + wn + nt * 8 + tig * 2;
            #pragma unroll
            for (int half = 0; half < 2; half++) {
                const int r = r0 + half * 8;
                const float d0 = acc[mt][nt][half * 2 + 0];
                const float d1 = acc[mt][nt][half * 2 + 1];
                const size_t o = (size_t)r * 4096 + col;
                if (MODE == 0) {
                    *(float2*)(out + o) = make_float2(d0, d1);
                    const float r0f = fmaxf(d0, 0.f), r1f = fmaxf(d1, 0.f);
                    union { __nv_bfloat16 b[2]; uint32_t u; } H, L;
                    H.b[0] = __float2bfloat16_rn(r0f);
                    H.b[1] = __float2bfloat16_rn(r1f);
                    L.b[0] = __float2bfloat16_rn(r0f - __bfloat162float(H.b[0]));
                    L.b[1] = __float2bfloat16_rn(r1f - __bfloat162float(H.b[1]));
                    *(uint32_t*)(ohi + o) = H.u;
                    *(uint32_t*)(olo + o) = L.u;
                } else {
                    const float2 fa = *(const float2*)(fast + o);
                    float2 v;
                    v.x = FAST_DECAY * fa.x + FAST_LR * (d0 * inv_tok);
                    v.y = FAST_DECAY * fa.y + FAST_LR * (d1 * inv_tok);
                    *(float2*)(out + o) = v;
                    ss += (double)v.x * v.x + (double)v.y * v.y;
                }
            }
        }
    }
    if (MODE == 1) {
        dred[tid] = ss;
        __syncthreads();
        #pragma unroll
        for (int off = 128; off > 0; off >>= 1) {
            if (tid < off) dred[tid] += dred[tid + off];
            __syncthreads();
        }
        if (tid == 0) g_partials[blockIdx.x] = dred[0];
    }
}

// ---------------------------------------------------------------------------
__global__ void k_norm_factor()
{
    __shared__ double red[256];
    const int tid = threadIdx.x;
    double s = 0.0;
    for (int i = tid; i < NTILES; i += 256) s += g_partials[i];
    red[tid] = s;
    __syncthreads();
    #pragma unroll
    for (int off = 128; off > 0; off >>= 1) {
        if (tid < off) red[tid] += red[tid + off];
        __syncthreads();
    }
    if (tid == 0) {
        const double norm = sqrt(red[0]);
        g_factor = (norm > HOMEO_TARGET) ? (float)(HOMEO_TARGET / (norm + 1e-6)) : 1.0f;
    }
}

__global__ __launch_bounds__(256) void k_finalize(
    const float* __restrict__ slow, float* __restrict__ fout, float* __restrict__ sout)
{
    const float fac = g_factor;
    const size_t i = (size_t)blockIdx.x * blockDim.x + threadIdx.x;
    float4 f = ((const float4*)fout)[i];
    f.x *= fac; f.y *= fac; f.z *= fac; f.w *= fac;
    ((float4*)fout)[i] = f;
    const float4 sl = ((const float4*)slow)[i];
    float4 so;
    so.x = SLOW_DECAY * sl.x + SLOW_LR * f.x;
    so.y = SLOW_DECAY * sl.y + SLOW_LR * f.y;
    so.z = SLOW_DECAY * sl.z + SLOW_LR * f.z;
    so.w = SLOW_DECAY * sl.w + SLOW_LR * f.w;
    ((float4*)sout)[i] = so;
}

// ---------------------------------------------------------------------------
typedef CUresult (*PFN_tmEncode)(
    CUtensorMap*, CUtensorMapDataType, cuuint32_t, void*,
    const cuuint64_t*, const cuuint64_t*, const cuuint32_t*, const cuuint32_t*,
    CUtensorMapInterleave, CUtensorMapSwizzle, CUtensorMapL2promotion,
    CUtensorMapFloatOOBfill);

static void make_map(PFN_tmEncode enc, CUtensorMap* m, void* ptr,
                     int box_inner, int box_outer, CUtensorMapSwizzle swz)
{
    cuuint64_t dims[2]    = {4096, 4096};
    cuuint64_t strides[1] = {4096 * 2};
    cuuint32_t box[2]     = {(cuuint32_t)box_inner, (cuuint32_t)box_outer};
    cuuint32_t est[2]     = {1, 1};
    enc(m, CU_TENSOR_MAP_DATA_TYPE_BFLOAT16, 2, ptr, dims, strides, box, est,
        CU_TENSOR_MAP_INTERLEAVE_NONE, swz,
        CU_TENSOR_MAP_L2_PROMOTION_L2_128B, CU_TENSOR_MAP_FLOAT_OOB_FILL_NONE);
}

extern "C" void kernel_launch(void* const* d_in, const int* in_sizes, int n_in,
                              void* d_out, int out_size)
{
    const float* x    = (const float*)d_in[0];
    const float* w    = (const float*)d_in[1];
    const float* fast = (const float*)d_in[2];
    const float* slow = (const float*)d_in[3];

    float* out   = (float*)d_out;
    float* y_out = out;
    float* f_out = out + (size_t)TOK * DOUT;
    float* s_out = f_out + ELEMS;

    __nv_bfloat16 *whi, *wlo, *xhi, *xlo, *yrhi, *yrlo;
    cudaGetSymbolAddress((void**)&whi,  g_whi);
    cudaGetSymbolAddress((void**)&wlo,  g_wlo);
    cudaGetSymbolAddress((void**)&xhi,  g_xhi);
    cudaGetSymbolAddress((void**)&xlo,  g_xlo);
    cudaGetSymbolAddress((void**)&yrhi, g_yrhi);
    cudaGetSymbolAddress((void**)&yrlo, g_yrlo);

    // Driver entry point for tensor-map encoding (no -lcuda needed).
    void* sym = nullptr;
    cudaDriverEntryPointQueryResult qr;
    cudaGetDriverEntryPoint("cuTensorMapEncodeTiled", &sym, cudaEnableDefault, &qr);
    PFN_tmEncode enc = (PFN_tmEncode)sym;

    // NT maps (GEMM1): box {32 k-elems, 128 rows}, SW64
    CUtensorMap mXhi, mXlo, mWhi, mWlo;
    make_map(enc, &mXhi, xhi, 32, 128, CU_TENSOR_MAP_SWIZZLE_64B);
    make_map(enc, &mXlo, xlo, 32, 128, CU_TENSOR_MAP_SWIZZLE_64B);
    make_map(enc, &mWhi, whi, 32, 128, CU_TENSOR_MAP_SWIZZLE_64B);
    make_map(enc, &mWlo, wlo, 32, 128, CU_TENSOR_MAP_SWIZZLE_64B);
    // TT maps (GEMM2): box {64 cols, 32 k-rows}, SW128
    CUtensorMap mYhi, mYlo, mXThi, mXTlo;
    make_map(enc, &mYhi,  yrhi, 64, 32, CU_TENSOR_MAP_SWIZZLE_128B);
    make_map(enc, &mYlo,  yrlo, 64, 32, CU_TENSOR_MAP_SWIZZLE_128B);
    make_map(enc, &mXThi, xhi,  64, 32, CU_TENSOR_MAP_SWIZZLE_128B);
    make_map(enc, &mXTlo, xlo,  64, 32, CU_TENSOR_MAP_SWIZZLE_128B);

    cudaFuncSetAttribute(k_gemm_tma<0>, cudaFuncAttributeMaxDynamicSharedMemorySize, DYN_SMEM);
    cudaFuncSetAttribute(k_gemm_tma<1>, cudaFuncAttributeMaxDynamicSharedMemorySize, DYN_SMEM);

    // 1) fused prep: w_eff quantize+split AND X split
    k_prep<<<4096 + 16384, 256>>>(w, fast, slow, x, whi, wlo, xhi, xlo);
    // 2) Y = X @ w_eff^T (TMA); epilogue emits relu(Y) bf16 hi/lo
    k_gemm_tma<0><<<NTILES, 256, DYN_SMEM>>>(mXhi, mXlo, mWhi, mWlo,
                                             nullptr, y_out, yrhi, yrlo);
    // 3) new_fast (unscaled) = 0.95*fast + 0.05*(reluY^T @ X)/TOK (TMA), + partials
    k_gemm_tma<1><<<NTILES, 256, DYN_SMEM>>>(mYhi, mYlo, mXThi, mXTlo,
                                             fast, f_out, nullptr, nullptr);
    // 4) norm -> factor
    k_norm_factor<<<1, 256>>>();
    // 5) scale fast, compute slow
    k_finalize<<<(unsigned)(ELEMS / 4 / 256), 256>>>(slow, f_out, s_out);
}

// round 14
// speedup vs baseline: 3.2920x; 2.4134x over previous
#include <cuda_runtime.h>
#include <cuda.h>
#include <cuda_fp16.h>
#include <stdint.h>
#include <math.h>

// ---------------------------------------------------------------------------
// Shapes (fixed)
#define TOK   4096
#define DIN   4096
#define DOUT  4096
#define ELEMS ((size_t)DOUT * (size_t)DIN)

#define FAST_DECAY 0.95f
#define FAST_LR    0.05f
#define SLOW_DECAY 0.99f
#define SLOW_LR    0.01f
#define HOMEO_TARGET 5.0

// fp16 single-term GEMM. CTA tile 128x128x64, 8 warps (4m x 2n), warp 32x64,
// TMA + 3-stage mbarrier pipeline, 2 CTAs/SM.
#define BK       64
#define NCHUNK   (4096 / BK)         // 64
#define NTILES   1024
#define TILE_B   16384               // one operand tile: 128 rows x 128B (SW128)
#define STAGE_B  (2 * TILE_B)        // A + B = 32KB
#define NSTAGE   3
#define DYN_SMEM (NSTAGE * STAGE_B + 1024)   // 99328; x2 CTAs = 198656 < 228KB

// ---------------------------------------------------------------------------
// Scratch
__device__ __half g_wh[ELEMS];       // w_eff fp16, K-major
__device__ __half g_xh[ELEMS];       // X fp16 [TOK, DIN]
__device__ __half g_yrh[ELEMS];      // relu(Y) fp16 [TOK, DOUT]
__device__ double g_partials[NTILES];
__device__ float  g_factor;

// ---------------------------------------------------------------------------
__device__ __forceinline__ uint32_t smem_u32(const void* p) {
    uint32_t a;
    asm("{ .reg .u64 t; cvta.to.shared.u64 t, %1; cvt.u32.u64 %0, t; }" : "=r"(a) : "l"(p));
    return a;
}
__device__ __forceinline__ void mma_f16(float* c, const uint32_t* a, const uint32_t* b) {
    asm volatile(
        "mma.sync.aligned.m16n8k16.row.col.f32.f16.f16.f32 "
        "{%0,%1,%2,%3}, {%4,%5,%6,%7}, {%8,%9}, {%0,%1,%2,%3};"
        : "+f"(c[0]), "+f"(c[1]), "+f"(c[2]), "+f"(c[3])
        : "r"(a[0]), "r"(a[1]), "r"(a[2]), "r"(a[3]), "r"(b[0]), "r"(b[1]));
}
#define LDSM4(R, A) \
    asm volatile("ldmatrix.sync.aligned.m8n8.x4.shared.b16 {%0,%1,%2,%3}, [%4];" \
        : "=r"((R)[0]), "=r"((R)[1]), "=r"((R)[2]), "=r"((R)[3]) : "r"(A))
#define LDSM4T(R, A) \
    asm volatile("ldmatrix.sync.aligned.m8n8.x4.trans.shared.b16 {%0,%1,%2,%3}, [%4];" \
        : "=r"((R)[0]), "=r"((R)[1]), "=r"((R)[2]), "=r"((R)[3]) : "r"(A))

#define MBARRIER_INIT(addr, cnt) \
    asm volatile("mbarrier.init.shared.b64 [%0], %1;" :: "r"(addr), "r"((uint32_t)(cnt)) : "memory")
#define MBARRIER_EXPECT_TX(addr, bytes) \
    asm volatile("mbarrier.arrive.expect_tx.shared.b64 _, [%0], %1;" \
                 :: "r"(addr), "r"((uint32_t)(bytes)) : "memory")
#define MBARRIER_WAIT_PARITY(addr, par) do {                                          \
    uint32_t _m = (addr); uint32_t _p = (uint32_t)(par); uint32_t _d;                 \
    asm volatile("{\n\t.reg .pred p;\n\t"                                             \
        "mbarrier.try_wait.parity.acquire.cta.shared::cta.b64 p, [%1], %2;\n\t"       \
        "selp.b32 %0, 1, 0, p;\n\t}" : "=r"(_d) : "r"(_m), "r"(_p) : "memory");       \
    if (!_d) {                                                                        \
        asm volatile("{\n\t.reg .pred P1;\n\t"                                        \
            "W_%=:\n\t"                                                               \
            "mbarrier.try_wait.parity.acquire.cta.shared::cta.b64 P1, [%0], %1, 0x989680;\n\t" \
            "@P1 bra.uni D_%=;\n\t"                                                   \
            "bra.uni W_%=;\n\t"                                                       \
            "D_%=:\n\t}" :: "r"(_m), "r"(_p) : "memory");                             \
    }                                                                                 \
} while (0)

__device__ __forceinline__ void tma2d(uint32_t dst, const CUtensorMap* m,
                                      int cx, int cy, uint32_t mbar) {
    asm volatile(
        "cp.async.bulk.tensor.2d.shared::cta.global.tile.mbarrier::complete_tx::bytes "
        "[%0], [%1, {%2, %3}], [%4];"
        :: "r"(dst), "l"(m), "r"(cx), "r"(cy), "r"(mbar) : "memory");
}

// ---------------------------------------------------------------------------
// Fused prep: blocks [0,4096): per-row quantize+combine w_eff -> wh (fp16)
//             blocks [4096,20480): X -> xh (fp16)
__global__ __launch_bounds__(256) void k_prep(
    const float* __restrict__ w, const float* __restrict__ fast, const float* __restrict__ slow,
    const float* __restrict__ x,
    __half* __restrict__ wh, __half* __restrict__ xh)
{
    const int tid = threadIdx.x;
    if (blockIdx.x >= 4096) {
        const size_t i = ((size_t)(blockIdx.x - 4096) * 256 + tid) * 4;
        float4 v = *(const float4*)(x + i);
        union { __half h[4]; uint64_t u; } H;
        H.h[0] = __float2half_rn(v.x);
        H.h[1] = __float2half_rn(v.y);
        H.h[2] = __float2half_rn(v.z);
        H.h[3] = __float2half_rn(v.w);
        *(uint64_t*)(xh + i) = H.u;
        return;
    }
    const int row = blockIdx.x;
    const size_t base = (size_t)row * DIN;

    float s = 0.f;
    for (int i = tid; i < DIN; i += 256) s += fabsf(w[base + i]);
    __shared__ float red[256];
    red[tid] = s;
    __syncthreads();
    #pragma unroll
    for (int off = 128; off > 0; off >>= 1) {
        if (tid < off) red[tid] += red[tid + off];
        __syncthreads();
    }
    float scale = fmaxf(red[0] * (1.0f / (float)DIN), 1e-5f);
    const float inv_scale = 1.0f / scale;

    for (int i = tid; i < DIN; i += 256) {
        const size_t idx = base + i;
        float q = rintf(w[idx] * inv_scale);
        q = fminf(fmaxf(q, -1.0f), 1.0f);
        float v = q * scale + 0.1f * fast[idx] + 0.05f * slow[idx];
        wh[idx] = __float2half_rn(v);
    }
}

// ---------------------------------------------------------------------------
// fp16 GEMM with TMA + 3-stage mbarrier pipeline, fp32 accumulators.
// MODE 0 (NT): tiles 128 rows x 128B (64 k-elems), SW128.
//              D[m][n] = sum_k A[am+m][k]*B[bn+n][k]; epilogue y fp32 + relu fp16.
// MODE 1 (TT): tiles 2 subtiles of 64 k-rows x 128B (64 cols), SW128, ldmatrix.trans.
//              D[m][n] = sum_k A[k][am+m]*B[k][bn+n]; epilogue EMA + sumsq partials.
// ---------------------------------------------------------------------------
template<int MODE>
__global__ __launch_bounds__(256, 2) void k_gemm_tma(
    const __grid_constant__ CUtensorMap mA, const __grid_constant__ CUtensorMap mB,
    const float* __restrict__ fast, float* __restrict__ out,
    __half* __restrict__ orelu)
{
    constexpr bool TRANS = (MODE == 1);

    extern __shared__ uint32_t dsm[];
    __shared__ double dred[256];
    __shared__ __align__(8) uint64_t mbars[NSTAGE];

    const int tid  = threadIdx.x;
    const int lane = tid & 31;
    const int wid  = tid >> 5;
    const int g    = lane >> 2;
    const int tig  = lane & 3;

    // supertile swizzle: 4 groups x (32 m-tiles x 8 n-tiles)
    const int bid   = blockIdx.x;
    const int group = bid >> 8;
    const int rem   = bid & 255;
    const int am  = (rem >> 3) * 128;
    const int bn  = (group * 8 + (rem & 7)) * 128;

    const int wm = (wid & 3) * 32;
    const int wn = (wid >> 2) * 64;

    const uint32_t sraw = smem_u32(dsm);
    const uint32_t sbase = (sraw + 1023u) & ~1023u;

    uint32_t mb[NSTAGE];
    #pragma unroll
    for (int s = 0; s < NSTAGE; s++) mb[s] = smem_u32(&mbars[s]);
    if (tid == 0) {
        #pragma unroll
        for (int s = 0; s < NSTAGE; s++) MBARRIER_INIT(mb[s], 1);
    }
    __syncthreads();

    // ---- per-lane ldmatrix offsets ----
    uint32_t aoff[2], boff[4];
    uint32_t asw[2], bsw[4];                 // NT swizzle selectors (r & 7)
    const int ld_row = ((lane >> 3) & 1) * 8 + (lane & 7);
    const int lh = lane >> 4;                // 16B-unit select (NT)
    if (!TRANS) {
        #pragma unroll
        for (int mt = 0; mt < 2; mt++) {
            const int r = wm + mt * 16 + ld_row;
            aoff[mt] = (uint32_t)(r * 128);
            asw[mt]  = (uint32_t)(r & 7);
        }
        #pragma unroll
        for (int p = 0; p < 4; p++) {
            const int r = wn + p * 16 + ld_row;
            boff[p] = (uint32_t)(r * 128);
            bsw[p]  = (uint32_t)(r & 7);
        }
    } else {
        const int kr = (lane >> 4) * 8 + (lane & 7);   // k row 0..15
        const int cb16 = ((lane >> 3) & 1) * 16;       // 16B col half
        #pragma unroll
        for (int mt = 0; mt < 2; mt++) {
            const int colb = wm * 2 + mt * 32 + cb16;  // byte col 0..255
            aoff[mt] = (uint32_t)((colb >> 7) * 8192 + kr * 128 +
                                  ((((colb & 127) >> 4) ^ (kr & 7)) << 4));
        }
        #pragma unroll
        for (int p = 0; p < 4; p++) {
            const int colb = wn * 2 + p * 32 + cb16;
            boff[p] = (uint32_t)((colb >> 7) * 8192 + kr * 128 +
                                 ((((colb & 127) >> 4) ^ (kr & 7)) << 4));
        }
    }

    float acc[2][8][4];
    #pragma unroll
    for (int mt = 0; mt < 2; mt++)
        #pragma unroll
        for (int nt = 0; nt < 8; nt++)
            #pragma unroll
            for (int r = 0; r < 4; r++) acc[mt][nt][r] = 0.f;

    // ---- TMA issue helper ----
    auto issue = [&](int stage, int chunk) {
        const uint32_t sdst = sbase + (uint32_t)stage * STAGE_B;
        MBARRIER_EXPECT_TX(mb[stage], STAGE_B);
        const int k0 = chunk * BK;
        if (!TRANS) {
            tma2d(sdst,          &mA, k0, am, mb[stage]);
            tma2d(sdst + TILE_B, &mB, k0, bn, mb[stage]);
        } else {
            tma2d(sdst,                 &mA, am,      k0, mb[stage]);
            tma2d(sdst + 8192,          &mA, am + 64, k0, mb[stage]);
            tma2d(sdst + TILE_B,        &mB, bn,      k0, mb[stage]);
            tma2d(sdst + TILE_B + 8192, &mB, bn + 64, k0, mb[stage]);
        }
    };

    if (tid == 0) { issue(0, 0); issue(1, 1); }

    int sc = 0;
    uint32_t phb = 0;
    for (int c = 0; c < NCHUNK; c++) {
        MBARRIER_WAIT_PARITY(mb[sc], (phb >> sc) & 1u);
        phb ^= (1u << sc);
        __syncthreads();   // all warps done with chunk c-1 (its stage may be refilled)
        if (c + 2 < NCHUNK) {
            int sn = sc + 2; if (sn >= NSTAGE) sn -= NSTAGE;
            if (tid == 0) issue(sn, c + 2);
        }

        const uint32_t stg = sbase + (uint32_t)sc * STAGE_B;
        #pragma unroll
        for (int ks = 0; ks < 4; ks++) {
            uint32_t a[2][4];
            #pragma unroll
            for (int mt = 0; mt < 2; mt++) {
                uint32_t addr;
                if (!TRANS)
                    addr = stg + aoff[mt] +
                           ((((uint32_t)(ks * 2 + lh)) ^ asw[mt]) << 4);
                else
                    addr = stg + aoff[mt] + ks * 2048;
                if (!TRANS) { LDSM4(a[mt], addr); } else { LDSM4T(a[mt], addr); }
            }
            uint32_t b[4][4];
            #pragma unroll
            for (int p = 0; p < 4; p++) {
                uint32_t addr;
                if (!TRANS)
                    addr = stg + TILE_B + boff[p] +
                           ((((uint32_t)(ks * 2 + lh)) ^ bsw[p]) << 4);
                else
                    addr = stg + TILE_B + boff[p] + ks * 2048;
                if (!TRANS) { LDSM4(b[p], addr); } else { LDSM4T(b[p], addr); }
            }
            #pragma unroll
            for (int p = 0; p < 4; p++) {
                uint32_t b0[2] = {b[p][0], b[p][2]}, b1[2] = {b[p][1], b[p][3]};
                mma_f16(acc[0][2*p],   a[0], b0);
                mma_f16(acc[0][2*p+1], a[0], b1);
                mma_f16(acc[1][2*p],   a[1], b0);
                mma_f16(acc[1][2*p+1], a[1], b1);
            }
        }
        sc = (sc == NSTAGE - 1) ? 0 : sc + 1;
    }

    // ---- epilogue ----
    double ss = 0.0;
    const float inv_tok = 1.0f / (float)TOK;
    #pragma unroll
    for (int mt = 0; mt < 2; mt++) {
        const int r0 = am + wm + mt * 16 + g;
        #pragma unroll
        for (int nt = 0; nt < 8; nt++) {
            const int col = bn + wn + nt * 8 + tig * 2;
            #pragma unroll
            for (int half = 0; half < 2; half++) {
                const int r = r0 + half * 8;
                const float d0 = acc[mt][nt][half * 2 + 0];
                const float d1 = acc[mt][nt][half * 2 + 1];
                const size_t o = (size_t)r * 4096 + col;
                if (MODE == 0) {
                    *(float2*)(out + o) = make_float2(d0, d1);
                    union { __half h[2]; uint32_t u; } R;
                    R.h[0] = __float2half_rn(fmaxf(d0, 0.f));
                    R.h[1] = __float2half_rn(fmaxf(d1, 0.f));
                    *(uint32_t*)(orelu + o) = R.u;
                } else {
                    const float2 fa = *(const float2*)(fast + o);
                    float2 v;
                    v.x = FAST_DECAY * fa.x + FAST_LR * (d0 * inv_tok);
                    v.y = FAST_DECAY * fa.y + FAST_LR * (d1 * inv_tok);
                    *(float2*)(out + o) = v;
                    ss += (double)v.x * v.x + (double)v.y * v.y;
                }
            }
        }
    }
    if (MODE == 1) {
        dred[tid] = ss;
        __syncthreads();
        #pragma unroll
        for (int off = 128; off > 0; off >>= 1) {
            if (tid < off) dred[tid] += dred[tid + off];
            __syncthreads();
        }
        if (tid == 0) g_partials[blockIdx.x] = dred[0];
    }
}

// ---------------------------------------------------------------------------
__global__ void k_norm_factor()
{
    __shared__ double red[256];
    const int tid = threadIdx.x;
    double s = 0.0;
    for (int i = tid; i < NTILES; i += 256) s += g_partials[i];
    red[tid] = s;
    __syncthreads();
    #pragma unroll
    for (int off = 128; off > 0; off >>= 1) {
        if (tid < off) red[tid] += red[tid + off];
        __syncthreads();
    }
    if (tid == 0) {
        const double norm = sqrt(red[0]);
        g_factor = (norm > HOMEO_TARGET) ? (float)(HOMEO_TARGET / (norm + 1e-6)) : 1.0f;
    }
}

__global__ __launch_bounds__(256) void k_finalize(
    const float* __restrict__ slow, float* __restrict__ fout, float* __restrict__ sout)
{
    const float fac = g_factor;
    const size_t i = (size_t)blockIdx.x * blockDim.x + threadIdx.x;
    float4 f = ((const float4*)fout)[i];
    f.x *= fac; f.y *= fac; f.z *= fac; f.w *= fac;
    ((float4*)fout)[i] = f;
    const float4 sl = ((const float4*)slow)[i];
    float4 so;
    so.x = SLOW_DECAY * sl.x + SLOW_LR * f.x;
    so.y = SLOW_DECAY * sl.y + SLOW_LR * f.y;
    so.z = SLOW_DECAY * sl.z + SLOW_LR * f.z;
    so.w = SLOW_DECAY * sl.w + SLOW_LR * f.w;
    ((float4*)sout)[i] = so;
}

// ---------------------------------------------------------------------------
typedef CUresult (*PFN_tmEncode)(
    CUtensorMap*, CUtensorMapDataType, cuuint32_t, void*,
    const cuuint64_t*, const cuuint64_t*, const cuuint32_t*, const cuuint32_t*,
    CUtensorMapInterleave, CUtensorMapSwizzle, CUtensorMapL2promotion,
    CUtensorMapFloatOOBfill);

static void make_map(PFN_tmEncode enc, CUtensorMap* m, void* ptr,
                     int box_inner, int box_outer)
{
    cuuint64_t dims[2]    = {4096, 4096};
    cuuint64_t strides[1] = {4096 * 2};
    cuuint32_t box[2]     = {(cuuint32_t)box_inner, (cuuint32_t)box_outer};
    cuuint32_t est[2]     = {1, 1};
    enc(m, CU_TENSOR_MAP_DATA_TYPE_FLOAT16, 2, ptr, dims, strides, box, est,
        CU_TENSOR_MAP_INTERLEAVE_NONE, CU_TENSOR_MAP_SWIZZLE_128B,
        CU_TENSOR_MAP_L2_PROMOTION_L2_128B, CU_TENSOR_MAP_FLOAT_OOB_FILL_NONE);
}

extern "C" void kernel_launch(void* const* d_in, const int* in_sizes, int n_in,
                              void* d_out, int out_size)
{
    const float* x    = (const float*)d_in[0];
    const float* w    = (const float*)d_in[1];
    const float* fast = (const float*)d_in[2];
    const float* slow = (const float*)d_in[3];

    float* out   = (float*)d_out;
    float* y_out = out;
    float* f_out = out + (size_t)TOK * DOUT;
    float* s_out = f_out + ELEMS;

    __half *wh, *xh, *yrh;
    cudaGetSymbolAddress((void**)&wh,  g_wh);
    cudaGetSymbolAddress((void**)&xh,  g_xh);
    cudaGetSymbolAddress((void**)&yrh, g_yrh);

    void* sym = nullptr;
    cudaDriverEntryPointQueryResult qr;
    cudaGetDriverEntryPoint("cuTensorMapEncodeTiled", &sym, cudaEnableDefault, &qr);
    PFN_tmEncode enc = (PFN_tmEncode)sym;

    // NT maps (GEMM1): box {64 k-elems, 128 rows}
    CUtensorMap mX, mW;
    make_map(enc, &mX, xh, 64, 128);
    make_map(enc, &mW, wh, 64, 128);
    // TT maps (GEMM2): box {64 cols, 64 k-rows}
    CUtensorMap mY, mXT;
    make_map(enc, &mY,  yrh, 64, 64);
    make_map(enc, &mXT, xh,  64, 64);

    cudaFuncSetAttribute(k_gemm_tma<0>, cudaFuncAttributeMaxDynamicSharedMemorySize, DYN_SMEM);
    cudaFuncSetAttribute(k_gemm_tma<1>, cudaFuncAttributeMaxDynamicSharedMemorySize, DYN_SMEM);

    // 1) fused prep: w_eff quantize->fp16 AND X->fp16
    k_prep<<<4096 + 16384, 256>>>(w, fast, slow, x, wh, xh);
    // 2) Y = X @ w_eff^T (fp16 TMA); epilogue emits y fp32 + relu(Y) fp16
    k_gemm_tma<0><<<NTILES, 256, DYN_SMEM>>>(mX, mW, nullptr, y_out, yrh);
    // 3) new_fast (unscaled) = 0.95*fast + 0.05*(reluY^T @ X)/TOK, + partials
    k_gemm_tma<1><<<NTILES, 256, DYN_SMEM>>>(mY, mXT, fast, f_out, nullptr);
    // 4) norm -> factor
    k_norm_factor<<<1, 256>>>();
    // 5) scale fast, compute slow
    k_finalize<<<(unsigned)(ELEMS / 4 / 256), 256>>>(slow, f_out, s_out);
}

// round 15
// speedup vs baseline: 3.3667x; 1.0227x over previous
#include <cuda_runtime.h>
#include <cuda.h>
#include <cuda_fp16.h>
#include <stdint.h>
#include <math.h>

// ---------------------------------------------------------------------------
// Shapes (fixed)
#define TOK   4096
#define DIN   4096
#define DOUT  4096
#define ELEMS ((size_t)DOUT * (size_t)DIN)

#define FAST_DECAY 0.95f
#define FAST_LR    0.05f
#define SLOW_DECAY 0.99f
#define SLOW_LR    0.01f
#define HOMEO_TARGET 5.0

// fp16 single-term GEMM. CTA tile 128x128x64, 8 warps (4m x 2n), warp 32x64,
// TMA + 3-stage full/empty mbarrier pipeline (no per-chunk CTA barrier), 2 CTAs/SM.
#define BK       64
#define NCHUNK   (4096 / BK)         // 64
#define NTILES   1024
#define TILE_B   16384               // one operand tile: 128 rows x 128B (SW128)
#define STAGE_B  (2 * TILE_B)        // A + B = 32KB
#define NSTAGE   3
#define DYN_SMEM (NSTAGE * STAGE_B + 1024)   // 99328; x2 CTAs = 198656 < 228KB

// ---------------------------------------------------------------------------
// Scratch
__device__ __half g_wh[ELEMS];       // w_eff fp16, K-major
__device__ __half g_xh[ELEMS];       // X fp16 [TOK, DIN]
__device__ __half g_yrh[ELEMS];      // relu(Y) fp16 [TOK, DOUT]
__device__ double g_partials[NTILES];
__device__ float  g_factor;

// ---------------------------------------------------------------------------
__device__ __forceinline__ uint32_t smem_u32(const void* p) {
    uint32_t a;
    asm("{ .reg .u64 t; cvta.to.shared.u64 t, %1; cvt.u32.u64 %0, t; }" : "=r"(a) : "l"(p));
    return a;
}
__device__ __forceinline__ void mma_f16(float* c, const uint32_t* a, const uint32_t* b) {
    asm volatile(
        "mma.sync.aligned.m16n8k16.row.col.f32.f16.f16.f32 "
        "{%0,%1,%2,%3}, {%4,%5,%6,%7}, {%8,%9}, {%0,%1,%2,%3};"
        : "+f"(c[0]), "+f"(c[1]), "+f"(c[2]), "+f"(c[3])
        : "r"(a[0]), "r"(a[1]), "r"(a[2]), "r"(a[3]), "r"(b[0]), "r"(b[1]));
}
#define LDSM4(R, A) \
    asm volatile("ldmatrix.sync.aligned.m8n8.x4.shared.b16 {%0,%1,%2,%3}, [%4];" \
        : "=r"((R)[0]), "=r"((R)[1]), "=r"((R)[2]), "=r"((R)[3]) : "r"(A))
#define LDSM4T(R, A) \
    asm volatile("ldmatrix.sync.aligned.m8n8.x4.trans.shared.b16 {%0,%1,%2,%3}, [%4];" \
        : "=r"((R)[0]), "=r"((R)[1]), "=r"((R)[2]), "=r"((R)[3]) : "r"(A))

#define MBARRIER_INIT(addr, cnt) \
    asm volatile("mbarrier.init.shared.b64 [%0], %1;" :: "r"(addr), "r"((uint32_t)(cnt)) : "memory")
#define MBARRIER_ARRIVE(addr) \
    asm volatile("mbarrier.arrive.shared.b64 _, [%0];" :: "r"(addr) : "memory")
#define MBARRIER_EXPECT_TX(addr, bytes) \
    asm volatile("mbarrier.arrive.expect_tx.shared.b64 _, [%0], %1;" \
                 :: "r"(addr), "r"((uint32_t)(bytes)) : "memory")
#define MBARRIER_WAIT_PARITY(addr, par) do {                                          \
    uint32_t _m = (addr); uint32_t _p = (uint32_t)(par); uint32_t _d;                 \
    asm volatile("{\n\t.reg .pred p;\n\t"                                             \
        "mbarrier.try_wait.parity.acquire.cta.shared::cta.b64 p, [%1], %2;\n\t"       \
        "selp.b32 %0, 1, 0, p;\n\t}" : "=r"(_d) : "r"(_m), "r"(_p) : "memory");       \
    if (!_d) {                                                                        \
        asm volatile("{\n\t.reg .pred P1;\n\t"                                        \
            "W_%=:\n\t"                                                               \
            "mbarrier.try_wait.parity.acquire.cta.shared::cta.b64 P1, [%0], %1, 0x989680;\n\t" \
            "@P1 bra.uni D_%=;\n\t"                                                   \
            "bra.uni W_%=;\n\t"                                                       \
            "D_%=:\n\t}" :: "r"(_m), "r"(_p) : "memory");                             \
    }                                                                                 \
} while (0)

__device__ __forceinline__ void tma2d(uint32_t dst, const CUtensorMap* m,
                                      int cx, int cy, uint32_t mbar) {
    asm volatile(
        "cp.async.bulk.tensor.2d.shared::cta.global.tile.mbarrier::complete_tx::bytes "
        "[%0], [%1, {%2, %3}], [%4];"
        :: "r"(dst), "l"(m), "r"(cx), "r"(cy), "r"(mbar) : "memory");
}

// ---------------------------------------------------------------------------
// Fused prep: blocks [0,4096): per-row quantize+combine w_eff -> wh (fp16)
//             blocks [4096,20480): X -> xh (fp16)
__global__ __launch_bounds__(256) void k_prep(
    const float* __restrict__ w, const float* __restrict__ fast, const float* __restrict__ slow,
    const float* __restrict__ x,
    __half* __restrict__ wh, __half* __restrict__ xh)
{
    const int tid = threadIdx.x;
    if (blockIdx.x >= 4096) {
        const size_t i = ((size_t)(blockIdx.x - 4096) * 256 + tid) * 4;
        float4 v = *(const float4*)(x + i);
        union { __half h[4]; uint64_t u; } H;
        H.h[0] = __float2half_rn(v.x);
        H.h[1] = __float2half_rn(v.y);
        H.h[2] = __float2half_rn(v.z);
        H.h[3] = __float2half_rn(v.w);
        *(uint64_t*)(xh + i) = H.u;
        return;
    }
    const int row = blockIdx.x;
    const size_t base = (size_t)row * DIN;

    float s = 0.f;
    for (int i = tid; i < DIN; i += 256) s += fabsf(w[base + i]);
    __shared__ float red[256];
    red[tid] = s;
    __syncthreads();
    #pragma unroll
    for (int off = 128; off > 0; off >>= 1) {
        if (tid < off) red[tid] += red[tid + off];
        __syncthreads();
    }
    float scale = fmaxf(red[0] * (1.0f / (float)DIN), 1e-5f);
    const float inv_scale = 1.0f / scale;

    for (int i = tid; i < DIN; i += 256) {
        const size_t idx = base + i;
        float q = rintf(w[idx] * inv_scale);
        q = fminf(fmaxf(q, -1.0f), 1.0f);
        float v = q * scale + 0.1f * fast[idx] + 0.05f * slow[idx];
        wh[idx] = __float2half_rn(v);
    }
}

// ---------------------------------------------------------------------------
// fp16 GEMM, TMA + 3-stage full/empty mbarrier pipeline, fp32 accumulators.
// MODE 0 (NT): tiles 128 rows x 128B (64 k-elems), SW128.
// MODE 1 (TT): 2 subtiles of 64 k-rows x 128B (64 cols), SW128, ldmatrix.trans.
// ---------------------------------------------------------------------------
template<int MODE>
__global__ __launch_bounds__(256, 2) void k_gemm_tma(
    const __grid_constant__ CUtensorMap mA, const __grid_constant__ CUtensorMap mB,
    const float* __restrict__ fast, float* __restrict__ out,
    __half* __restrict__ orelu)
{
    constexpr bool TRANS = (MODE == 1);

    extern __shared__ uint32_t dsm[];
    __shared__ double dred[256];
    __shared__ __align__(8) uint64_t mbars[2 * NSTAGE];   // [0..2]=full, [3..5]=empty

    const int tid  = threadIdx.x;
    const int lane = tid & 31;
    const int wid  = tid >> 5;
    const int g    = lane >> 2;
    const int tig  = lane & 3;

    // supertile swizzle: 4 groups x (32 m-tiles x 8 n-tiles)
    const int bid   = blockIdx.x;
    const int group = bid >> 8;
    const int rem   = bid & 255;
    const int am  = (rem >> 3) * 128;
    const int bn  = (group * 8 + (rem & 7)) * 128;

    const int wm = (wid & 3) * 32;
    const int wn = (wid >> 2) * 64;

    const uint32_t sraw = smem_u32(dsm);
    const uint32_t sbase = (sraw + 1023u) & ~1023u;

    uint32_t mbf[NSTAGE], mbe[NSTAGE];
    #pragma unroll
    for (int s = 0; s < NSTAGE; s++) {
        mbf[s] = smem_u32(&mbars[s]);
        mbe[s] = smem_u32(&mbars[NSTAGE + s]);
    }
    if (tid == 0) {
        #pragma unroll
        for (int s = 0; s < NSTAGE; s++) {
            MBARRIER_INIT(mbf[s], 1);
            MBARRIER_INIT(mbe[s], 8);    // one arrive per warp
        }
    }
    __syncthreads();

    // ---- per-lane ldmatrix offsets ----
    uint32_t aoff[2], boff[4];
    uint32_t asw[2], bsw[4];                 // NT swizzle selectors (r & 7)
    const int ld_row = ((lane >> 3) & 1) * 8 + (lane & 7);
    const int lh = lane >> 4;                // 16B-unit select (NT)
    if (!TRANS) {
        #pragma unroll
        for (int mt = 0; mt < 2; mt++) {
            const int r = wm + mt * 16 + ld_row;
            aoff[mt] = (uint32_t)(r * 128);
            asw[mt]  = (uint32_t)(r & 7);
        }
        #pragma unroll
        for (int p = 0; p < 4; p++) {
            const int r = wn + p * 16 + ld_row;
            boff[p] = (uint32_t)(r * 128);
            bsw[p]  = (uint32_t)(r & 7);
        }
    } else {
        const int kr = (lane >> 4) * 8 + (lane & 7);   // k row 0..15
        const int cb16 = ((lane >> 3) & 1) * 16;       // 16B col half
        #pragma unroll
        for (int mt = 0; mt < 2; mt++) {
            const int colb = wm * 2 + mt * 32 + cb16;  // byte col 0..255
            aoff[mt] = (uint32_t)((colb >> 7) * 8192 + kr * 128 +
                                  ((((colb & 127) >> 4) ^ (kr & 7)) << 4));
        }
        #pragma unroll
        for (int p = 0; p < 4; p++) {
            const int colb = wn * 2 + p * 32 + cb16;
            boff[p] = (uint32_t)((colb >> 7) * 8192 + kr * 128 +
                                 ((((colb & 127) >> 4) ^ (kr & 7)) << 4));
        }
    }

    float acc[2][8][4];
    #pragma unroll
    for (int mt = 0; mt < 2; mt++)
        #pragma unroll
        for (int nt = 0; nt < 8; nt++)
            #pragma unroll
            for (int r = 0; r < 4; r++) acc[mt][nt][r] = 0.f;

    // ---- TMA issue helper (thread 0 only) ----
    auto issue = [&](int stage, int chunk) {
        const uint32_t sdst = sbase + (uint32_t)stage * STAGE_B;
        MBARRIER_EXPECT_TX(mbf[stage], STAGE_B);
        const int k0 = chunk * BK;
        if (!TRANS) {
            tma2d(sdst,          &mA, k0, am, mbf[stage]);
            tma2d(sdst + TILE_B, &mB, k0, bn, mbf[stage]);
        } else {
            tma2d(sdst,                 &mA, am,      k0, mbf[stage]);
            tma2d(sdst + 8192,          &mA, am + 64, k0, mbf[stage]);
            tma2d(sdst + TILE_B,        &mB, bn,      k0, mbf[stage]);
            tma2d(sdst + TILE_B + 8192, &mB, bn + 64, k0, mbf[stage]);
        }
    };

    if (tid == 0) { issue(0, 0); issue(1, 1); }

    int sc = 0;
    uint32_t phb = 0;        // per-warp full-barrier phase bits
    for (int c = 0; c < NCHUNK; c++) {
        // Thread 0: refill pipeline 2 chunks ahead. Requires all warps to have
        // released stage (c+2)%3, i.e. finished computing chunk c-1.
        if (tid == 0 && c + 2 < NCHUNK) {
            const int cc = c + 2;
            int sn = sc + 2; if (sn >= NSTAGE) sn -= NSTAGE;
            const int u = cc / NSTAGE;           // use index of this stage
            if (u >= 1) MBARRIER_WAIT_PARITY(mbe[sn], (uint32_t)((u - 1) & 1));
            issue(sn, cc);
        }

        // All warps: wait for chunk c's data (independent, no CTA barrier).
        MBARRIER_WAIT_PARITY(mbf[sc], (phb >> sc) & 1u);
        phb ^= (1u << sc);

        const uint32_t stg = sbase + (uint32_t)sc * STAGE_B;
        #pragma unroll
        for (int ks = 0; ks < 4; ks++) {
            uint32_t a[2][4];
            #pragma unroll
            for (int mt = 0; mt < 2; mt++) {
                uint32_t addr;
                if (!TRANS)
                    addr = stg + aoff[mt] +
                           ((((uint32_t)(ks * 2 + lh)) ^ asw[mt]) << 4);
                else
                    addr = stg + aoff[mt] + ks * 2048;
                if (!TRANS) { LDSM4(a[mt], addr); } else { LDSM4T(a[mt], addr); }
            }
            uint32_t b[4][4];
            #pragma unroll
            for (int p = 0; p < 4; p++) {
                uint32_t addr;
                if (!TRANS)
                    addr = stg + TILE_B + boff[p] +
                           ((((uint32_t)(ks * 2 + lh)) ^ bsw[p]) << 4);
                else
                    addr = stg + TILE_B + boff[p] + ks * 2048;
                if (!TRANS) { LDSM4(b[p], addr); } else { LDSM4T(b[p], addr); }
            }
            #pragma unroll
            for (int p = 0; p < 4; p++) {
                uint32_t b0[2] = {b[p][0], b[p][2]}, b1[2] = {b[p][1], b[p][3]};
                mma_f16(acc[0][2*p],   a[0], b0);
                mma_f16(acc[0][2*p+1], a[0], b1);
                mma_f16(acc[1][2*p],   a[1], b0);
                mma_f16(acc[1][2*p+1], a[1], b1);
            }
        }
        // this warp is done reading stage sc (LDSM results are in registers)
        if (lane == 0) MBARRIER_ARRIVE(mbe[sc]);
        sc = (sc == NSTAGE - 1) ? 0 : sc + 1;
    }

    // ---- epilogue ----
    double ss = 0.0;
    const float inv_tok = 1.0f / (float)TOK;
    #pragma unroll
    for (int mt = 0; mt < 2; mt++) {
        const int r0 = am + wm + mt * 16 + g;
        #pragma unroll
        for (int nt = 0; nt < 8; nt++) {
            const int col = bn + wn + nt * 8 + tig * 2;
            #pragma unroll
            for (int half = 0; half < 2; half++) {
                const int r = r0 + half * 8;
                const float d0 = acc[mt][nt][half * 2 + 0];
                const float d1 = acc[mt][nt][half * 2 + 1];
                const size_t o = (size_t)r * 4096 + col;
                if (MODE == 0) {
                    *(float2*)(out + o) = make_float2(d0, d1);
                    union { __half h[2]; uint32_t u; } R;
                    R.h[0] = __float2half_rn(fmaxf(d0, 0.f));
                    R.h[1] = __float2half_rn(fmaxf(d1, 0.f));
                    *(uint32_t*)(orelu + o) = R.u;
                } else {
                    const float2 fa = *(const float2*)(fast + o);
                    float2 v;
                    v.x = FAST_DECAY * fa.x + FAST_LR * (d0 * inv_tok);
                    v.y = FAST_DECAY * fa.y + FAST_LR * (d1 * inv_tok);
                    *(float2*)(out + o) = v;
                    ss += (double)v.x * v.x + (double)v.y * v.y;
                }
            }
        }
    }
    if (MODE == 1) {
        dred[tid] = ss;
        __syncthreads();
        #pragma unroll
        for (int off = 128; off > 0; off >>= 1) {
            if (tid < off) dred[tid] += dred[tid + off];
            __syncthreads();
        }
        if (tid == 0) g_partials[blockIdx.x] = dred[0];
    }
}

// ---------------------------------------------------------------------------
__global__ void k_norm_factor()
{
    __shared__ double red[256];
    const int tid = threadIdx.x;
    double s = 0.0;
    for (int i = tid; i < NTILES; i += 256) s += g_partials[i];
    red[tid] = s;
    __syncthreads();
    #pragma unroll
    for (int off = 128; off > 0; off >>= 1) {
        if (tid < off) red[tid] += red[tid + off];
        __syncthreads();
    }
    if (tid == 0) {
        const double norm = sqrt(red[0]);
        g_factor = (norm > HOMEO_TARGET) ? (float)(HOMEO_TARGET / (norm + 1e-6)) : 1.0f;
    }
}

__global__ __launch_bounds__(256) void k_finalize(
    const float* __restrict__ slow, float* __restrict__ fout, float* __restrict__ sout)
{
    const float fac = g_factor;
    const size_t i = (size_t)blockIdx.x * blockDim.x + threadIdx.x;
    float4 f = ((const float4*)fout)[i];
    f.x *= fac; f.y *= fac; f.z *= fac; f.w *= fac;
    ((float4*)fout)[i] = f;
    const float4 sl = ((const float4*)slow)[i];
    float4 so;
    so.x = SLOW_DECAY * sl.x + SLOW_LR * f.x;
    so.y = SLOW_DECAY * sl.y + SLOW_LR * f.y;
    so.z = SLOW_DECAY * sl.z + SLOW_LR * f.z;
    so.w = SLOW_DECAY * sl.w + SLOW_LR * f.w;
    ((float4*)sout)[i] = so;
}

// ---------------------------------------------------------------------------
typedef CUresult (*PFN_tmEncode)(
    CUtensorMap*, CUtensorMapDataType, cuuint32_t, void*,
    const cuuint64_t*, const cuuint64_t*, const cuuint32_t*, const cuuint32_t*,
    CUtensorMapInterleave, CUtensorMapSwizzle, CUtensorMapL2promotion,
    CUtensorMapFloatOOBfill);

static void make_map(PFN_tmEncode enc, CUtensorMap* m, void* ptr,
                     int box_inner, int box_outer)
{
    cuuint64_t dims[2]    = {4096, 4096};
    cuuint64_t strides[1] = {4096 * 2};
    cuuint32_t box[2]     = {(cuuint32_t)box_inner, (cuuint32_t)box_outer};
    cuuint32_t est[2]     = {1, 1};
    enc(m, CU_TENSOR_MAP_DATA_TYPE_FLOAT16, 2, ptr, dims, strides, box, est,
        CU_TENSOR_MAP_INTERLEAVE_NONE, CU_TENSOR_MAP_SWIZZLE_128B,
        CU_TENSOR_MAP_L2_PROMOTION_L2_128B, CU_TENSOR_MAP_FLOAT_OOB_FILL_NONE);
}

extern "C" void kernel_launch(void* const* d_in, const int* in_sizes, int n_in,
                              void* d_out, int out_size)
{
    const float* x    = (const float*)d_in[0];
    const float* w    = (const float*)d_in[1];
    const float* fast = (const float*)d_in[2];
    const float* slow = (const float*)d_in[3];

    float* out   = (float*)d_out;
    float* y_out = out;
    float* f_out = out + (size_t)TOK * DOUT;
    float* s_out = f_out + ELEMS;

    __half *wh, *xh, *yrh;
    cudaGetSymbolAddress((void**)&wh,  g_wh);
    cudaGetSymbolAddress((void**)&xh,  g_xh);
    cudaGetSymbolAddress((void**)&yrh, g_yrh);

    void* sym = nullptr;
    cudaDriverEntryPointQueryResult qr;
    cudaGetDriverEntryPoint("cuTensorMapEncodeTiled", &sym, cudaEnableDefault, &qr);
    PFN_tmEncode enc = (PFN_tmEncode)sym;

    // NT maps (GEMM1): box {64 k-elems, 128 rows}
    CUtensorMap mX, mW;
    make_map(enc, &mX, xh, 64, 128);
    make_map(enc, &mW, wh, 64, 128);
    // TT maps (GEMM2): box {64 cols, 64 k-rows}
    CUtensorMap mY, mXT;
    make_map(enc, &mY,  yrh, 64, 64);
    make_map(enc, &mXT, xh,  64, 64);

    cudaFuncSetAttribute(k_gemm_tma<0>, cudaFuncAttributeMaxDynamicSharedMemorySize, DYN_SMEM);
    cudaFuncSetAttribute(k_gemm_tma<1>, cudaFuncAttributeMaxDynamicSharedMemorySize, DYN_SMEM);

    // 1) fused prep: w_eff quantize->fp16 AND X->fp16
    k_prep<<<4096 + 16384, 256>>>(w, fast, slow, x, wh, xh);
    // 2) Y = X @ w_eff^T (fp16 TMA); epilogue emits y fp32 + relu(Y) fp16
    k_gemm_tma<0><<<NTILES, 256, DYN_SMEM>>>(mX, mW, nullptr, y_out, yrh);
    // 3) new_fast (unscaled) = 0.95*fast + 0.05*(reluY^T @ X)/TOK, + partials
    k_gemm_tma<1><<<NTILES, 256, DYN_SMEM>>>(mY, mXT, fast, f_out, nullptr);
    // 4) norm -> factor
    k_norm_factor<<<1, 256>>>();
    // 5) scale fast, compute slow
    k_finalize<<<(unsigned)(ELEMS / 4 / 256), 256>>>(slow, f_out, s_out);
}